// round 10
// baseline (speedup 1.0000x reference)
#include <cuda_runtime.h>
#include <cuda_bf16.h>
#include <math.h>
#include <stdint.h>

// Problem constants
#define TT     256
#define BB     64
#define HH     512
#define FOURH  2048
#define KP     1024
#define MM     (TT*BB)     // 16384

// ---------------------------------------------------------------------------
// Device scratch (static only)
// ---------------------------------------------------------------------------
__device__ float g_xproj[(size_t)2*MM*FOURH];        // input projections, pr-packed cols
__device__ unsigned g_cnt[2][4];                     // per (dir, chunk) producer counters

// proj operands: bf16 split, row-major. Layer-1 A is written by lstm_mma.
__device__ __align__(16) __nv_bfloat16 g_Ahi[(size_t)MM*KP];
__device__ __align__(16) __nv_bfloat16 g_Alo[(size_t)MM*KP];
__device__ __align__(16) __nv_bfloat16 g_Whi[(size_t)4096*KP];
__device__ __align__(16) __nv_bfloat16 g_Wlo[(size_t)4096*KP];

// recurrence W_hh: per (dir, block) slab: hi[32][1040B] + lo[32][1040B]
#define WSLAB 66560
#define WLO   33280
__device__ __align__(128) char g_Wr[(size_t)2*64*WSLAB];

// recurrence h state: [dir][ping][chunk4]{ hi[64][272B], lo[64][272B] }
#define CH_HALF 17408
#define CH_SZ   34816
#define HA_SZ   (4*CH_SZ)    // 139264 per (dir,ping)
__device__ __align__(128) char g_hA[(size_t)2*2*HA_SZ];

// ---------------------------------------------------------------------------
// PTX helpers
// ---------------------------------------------------------------------------
__device__ __forceinline__ uint32_t smem_u32(const void* p) {
    uint32_t a;
    asm("{ .reg .u64 t; cvta.to.shared.u64 t, %1; cvt.u32.u64 %0, t; }" : "=r"(a) : "l"(p));
    return a;
}
__device__ __forceinline__ void mbar_init(uint32_t mb, uint32_t cnt) {
    asm volatile("mbarrier.init.shared.b64 [%0], %1;" :: "r"(mb), "r"(cnt) : "memory");
}
__device__ __forceinline__ void mbar_expect_tx(uint32_t mb, uint32_t bytes) {
    asm volatile("mbarrier.arrive.expect_tx.shared.b64 _, [%0], %1;" :: "r"(mb), "r"(bytes) : "memory");
}
__device__ __forceinline__ void bulk_g2s(uint32_t dst, const void* src, uint32_t bytes, uint32_t mb) {
    asm volatile("cp.async.bulk.shared::cta.global.mbarrier::complete_tx::bytes [%0], [%1], %2, [%3];"
                 :: "r"(dst), "l"(src), "r"(bytes), "r"(mb) : "memory");
}
__device__ __forceinline__ void mbar_wait(uint32_t mb, uint32_t parity) {
    uint32_t done;
    asm volatile("{\n\t.reg .pred p;\n\t"
        "mbarrier.try_wait.parity.acquire.cta.shared::cta.b64 p, [%1], %2;\n\t"
        "selp.b32 %0, 1, 0, p;\n\t}"
        : "=r"(done) : "r"(mb), "r"(parity) : "memory");
    while (!done) {
        asm volatile("{\n\t.reg .pred p;\n\t"
            "mbarrier.try_wait.parity.acquire.cta.shared::cta.b64 p, [%1], %2, 0x989680;\n\t"
            "selp.b32 %0, 1, 0, p;\n\t}"
            : "=r"(done) : "r"(mb), "r"(parity) : "memory");
    }
}
__device__ __forceinline__ void cpa16(uint32_t dst, const void* src) {
    asm volatile("cp.async.cg.shared.global [%0], [%1], 16;" :: "r"(dst), "l"(src) : "memory");
}
__device__ __forceinline__ void ldm_x4(uint32_t& r0, uint32_t& r1, uint32_t& r2, uint32_t& r3,
                                       uint32_t addr) {
    asm volatile("ldmatrix.sync.aligned.m8n8.x4.shared.b16 {%0,%1,%2,%3}, [%4];"
                 : "=r"(r0), "=r"(r1), "=r"(r2), "=r"(r3) : "r"(addr));
}
#define MMA_BF16(c, a, b0v, b1v) \
    asm volatile("mma.sync.aligned.m16n8k16.row.col.f32.bf16.bf16.f32 " \
        "{%0,%1,%2,%3}, {%4,%5,%6,%7}, {%8,%9}, {%0,%1,%2,%3};" \
        : "+f"((c)[0]), "+f"((c)[1]), "+f"((c)[2]), "+f"((c)[3]) \
        : "r"((a)[0]), "r"((a)[1]), "r"((a)[2]), "r"((a)[3]), "r"(b0v), "r"(b1v))

__device__ __forceinline__ float sig_(float x) {
    return __fdividef(1.f, 1.f + __expf(-x));
}
__device__ __forceinline__ uint32_t pack_hilo(float a, float b, uint32_t& lo) {
    __nv_bfloat16 h0 = __float2bfloat16(a);
    __nv_bfloat16 h1 = __float2bfloat16(b);
    __nv_bfloat16 l0 = __float2bfloat16(a - __bfloat162float(h0));
    __nv_bfloat16 l1 = __float2bfloat16(b - __bfloat162float(h1));
    lo = (uint32_t)__bfloat16_as_ushort(l0) | ((uint32_t)__bfloat16_as_ushort(l1) << 16);
    return (uint32_t)__bfloat16_as_ushort(h0) | ((uint32_t)__bfloat16_as_ushort(h1) << 16);
}

// ---------------------------------------------------------------------------
// Zero h slot 0 (both dirs) + producer counters
// ---------------------------------------------------------------------------
__global__ void zero_state() {
    uint32_t i = blockIdx.x * 256 + threadIdx.x;
    float* p = (float*)g_hA;
    if (i < HA_SZ / 4) {
        p[i] = 0.f;
        p[i + (2 * HA_SZ) / 4] = 0.f;
    }
    if (i < 8) ((unsigned*)g_cnt)[i] = 0u;
}

// ---------------------------------------------------------------------------
// Pack fp32 -> hi/lo bf16 (row-major, 8 elems/thread)
// ---------------------------------------------------------------------------
__global__ __launch_bounds__(256) void pack_bf16(
    const float* __restrict__ src,
    __nv_bfloat16* __restrict__ hi, __nv_bfloat16* __restrict__ lo)
{
    size_t i = ((size_t)blockIdx.x * 256 + threadIdx.x) * 8;
    float4 v0 = *(const float4*)(src + i);
    float4 v1 = *(const float4*)(src + i + 4);
    float xv[8] = {v0.x, v0.y, v0.z, v0.w, v1.x, v1.y, v1.z, v1.w};
    uint32_t hp[4], lp[4];
#pragma unroll
    for (int e = 0; e < 4; e++) hp[e] = pack_hilo(xv[2*e], xv[2*e+1], lp[e]);
    *(uint4*)(hi + i) = make_uint4(hp[0], hp[1], hp[2], hp[3]);
    *(uint4*)(lo + i) = make_uint4(lp[0], lp[1], lp[2], lp[3]);
}

// ---------------------------------------------------------------------------
// Pack W_hh into per-block slabs: row pr=hh*4+g  <-  W[g*512 + blk*8+hh][k]
// ---------------------------------------------------------------------------
__global__ __launch_bounds__(256) void pack_Wr(const float* __restrict__ whh) {
    const int dir = blockIdx.x >> 6, blk = blockIdx.x & 63;
    char* slab = g_Wr + (size_t)(dir * 64 + blk) * WSLAB;
    for (int i = threadIdx.x; i < 8192; i += 256) {
        int r = i >> 8;
        int k2 = (i & 255) * 2;
        int hh = r >> 2, g = r & 3;
        int grow = g * HH + blk * 8 + hh;
        float2 v = *(const float2*)&whh[((size_t)dir * FOURH + grow) * HH + k2];
        uint32_t lo, hi = pack_hilo(v.x, v.y, lo);
        *(uint32_t*)(slab + r * 1040 + k2 * 2) = hi;
        *(uint32_t*)(slab + WLO + r * 1040 + k2 * 2) = lo;
    }
}

// ---------------------------------------------------------------------------
// HMMA projection GEMM, 3-stage pipeline, CTA tile = 128 rows x 128 PR-cols.
// pr = hh*4+g; W natural row for pr: n = (pr&3)*512 + (pr>>2).
// ---------------------------------------------------------------------------
#define ROWB   144
#define TILEB  (128*ROWB)
#define STGB   (4*TILEB)                  // 73728
#define OFF_BIAS (3*STGB)                 // 221184
#define SMEM_PROJ (OFF_BIAS + 768)

__global__ __launch_bounds__(256, 1) void proj_mma(
    const __nv_bfloat16* __restrict__ Ah, const __nv_bfloat16* __restrict__ Al,
    const __nv_bfloat16* __restrict__ Wh, const __nv_bfloat16* __restrict__ Wl,
    const float* __restrict__ b1, const float* __restrict__ b2)
{
    extern __shared__ __align__(128) char smp[];
    const uint32_t sb = smem_u32(smp);
    float* bias = (float*)(smp + OFF_BIAS);

    const int tid  = threadIdx.x;
    const int lane = tid & 31;
    const int w    = tid >> 5;
    const int m0   = blockIdx.x * 128;
    const int dir  = blockIdx.y >> 4;
    const int prG  = (blockIdx.y & 15) * 128;
    const int prB  = prG >> 2;
    const int wm   = (w >> 2) * 64;
    const int wn   = (w & 3) * 32;

    if (tid < 128) {
        int n = (tid & 3) * 512 + prB + (tid >> 2);
        bias[tid] = b1[dir * FOURH + n] + b2[dir * FOURH + n];
    }

    int cr[16], cc[16], ct[16];
#pragma unroll
    for (int i = 0; i < 16; i++) {
        int c = i * 256 + tid;
        ct[i] = c >> 10; cr[i] = (c >> 3) & 127; cc[i] = c & 7;
    }

    auto load_stage = [&](int s, int kt) {
        uint32_t base = sb + (uint32_t)s * STGB;
#pragma unroll
        for (int i = 0; i < 16; i++) {
            uint32_t dst = base + (uint32_t)ct[i] * TILEB + (uint32_t)cr[i] * ROWB + (uint32_t)cc[i] * 16;
            const __nv_bfloat16* g;
            if (ct[i] == 0)      g = Ah + (size_t)(m0 + cr[i]) * KP + kt * 64 + cc[i] * 8;
            else if (ct[i] == 1) g = Al + (size_t)(m0 + cr[i]) * KP + kt * 64 + cc[i] * 8;
            else {
                int n = (cr[i] & 3) * 512 + prB + (cr[i] >> 2);
                const __nv_bfloat16* Wb = (ct[i] == 2) ? Wh : Wl;
                g = Wb + (size_t)(dir * FOURH + n) * KP + kt * 64 + cc[i] * 8;
            }
            cpa16(dst, g);
        }
        asm volatile("cp.async.commit_group;" ::: "memory");
    };

    float c[4][4][4];
#pragma unroll
    for (int mi = 0; mi < 4; mi++)
#pragma unroll
        for (int ni = 0; ni < 4; ni++)
#pragma unroll
            for (int j = 0; j < 4; j++) c[mi][ni][j] = 0.f;

    const uint32_t aRow  = (uint32_t)(wm + (lane & 15));
    const uint32_t aByte = (lane & 16) ? 16u : 0u;
    const uint32_t bRow  = (uint32_t)(wn + (lane & 7) + ((lane & 16) ? 8 : 0));
    const uint32_t bByte = (lane & 8) ? 16u : 0u;

    load_stage(0, 0);
    load_stage(1, 1);

    for (int kt = 0; kt < 16; kt++) {
        if (kt + 2 < 16) {
            load_stage((kt + 2) % 3, kt + 2);
            asm volatile("cp.async.wait_group 2;" ::: "memory");
        } else if (kt + 1 < 16) {
            asm volatile("cp.async.wait_group 1;" ::: "memory");
        } else {
            asm volatile("cp.async.wait_group 0;" ::: "memory");
        }
        __syncthreads();

        uint32_t st = sb + (uint32_t)(kt % 3) * STGB;
#pragma unroll
        for (int ks = 0; ks < 4; ks++) {
            uint32_t kb = (uint32_t)(ks * 32);
            uint32_t ah[4][4], al[4][4], bh[2][4], bl[2][4];
#pragma unroll
            for (int mi = 0; mi < 4; mi++) {
                uint32_t ra = (aRow + mi * 16) * ROWB + kb + aByte;
                ldm_x4(ah[mi][0], ah[mi][1], ah[mi][2], ah[mi][3], st + ra);
                ldm_x4(al[mi][0], al[mi][1], al[mi][2], al[mi][3], st + TILEB + ra);
            }
#pragma unroll
            for (int np = 0; np < 2; np++) {
                uint32_t rb = (bRow + np * 16) * ROWB + kb + bByte;
                ldm_x4(bh[np][0], bh[np][1], bh[np][2], bh[np][3], st + 2 * TILEB + rb);
                ldm_x4(bl[np][0], bl[np][1], bl[np][2], bl[np][3], st + 3 * TILEB + rb);
            }
#pragma unroll
            for (int mi = 0; mi < 4; mi++)
#pragma unroll
                for (int ni = 0; ni < 4; ni++) {
                    int np = ni >> 1, o = (ni & 1) * 2;
                    MMA_BF16(c[mi][ni], ah[mi], bh[np][o], bh[np][o + 1]);
                    MMA_BF16(c[mi][ni], ah[mi], bl[np][o], bl[np][o + 1]);
                    MMA_BF16(c[mi][ni], al[mi], bh[np][o], bh[np][o + 1]);
                }
        }
        __syncthreads();
    }

    float* outD = g_xproj + (size_t)dir * MM * FOURH;
#pragma unroll
    for (int mi = 0; mi < 4; mi++) {
        int row0 = m0 + wm + mi * 16 + (lane >> 2);
#pragma unroll
        for (int ni = 0; ni < 4; ni++) {
            int colL = wn + ni * 8 + (lane & 3) * 2;
            float bx = bias[colL], by = bias[colL + 1];
            *(float2*)&outD[(size_t)row0 * FOURH + prG + colL] =
                make_float2(c[mi][ni][0] + bx, c[mi][ni][1] + by);
            *(float2*)&outD[(size_t)(row0 + 8) * FOURH + prG + colL] =
                make_float2(c[mi][ni][2] + bx, c[mi][ni][3] + by);
        }
    }
}

// ---------------------------------------------------------------------------
// Persistent HMMA recurrence, K-split warp layout.
// grid = (64 blk, 2 dir), 256 threads (8 warps).
// Warp w: mpos = w&1 (m32), npos = (w>>1)&1 (n16), kh = w>>2 (K256 = chunks
// {2kh, 2kh+1}). 4 accumulator chains of 48 links per warp (was 2 x 96).
// kh1 partials reduced into kh0 via smem; kh0 warps run the cells.
// ---------------------------------------------------------------------------
#define SM_A   0                        // 4 chunks x (hi 17408 + lo 17408)
#define SM_W   139264                   // hi[32][1040] + lo[32][1040]
#define SM_RED 205824                   // 4 warps x 16 frags x 32 lanes fp32 = 8KB
#define SM_ST  214016                   // staging: hi 1KB | lo 1KB | f32 2KB
#define SM_MB  218112                   // 5 mbarriers
#define SMEM_LSTM 218176

__global__ __launch_bounds__(256, 1) void lstm_mma(
    const int* __restrict__ mask,     // [B][T]
    float*     __restrict__ outp,     // [T][B][2H] (mode 1)
    int mode)
{
    extern __shared__ __align__(128) char sm[];
    const uint32_t sb = smem_u32(sm);
    float*    sRed = (float*)(sm + SM_RED);
    uint16_t* sHhi = (uint16_t*)(sm + SM_ST);
    uint16_t* sHlo = (uint16_t*)(sm + SM_ST + 1024);
    float*    sF32 = (float*)(sm + SM_ST + 2048);

    const int dir = blockIdx.y;
    const int blk = blockIdx.x;
    const int tid = threadIdx.x;
    const int lane = tid & 31;
    const int w = tid >> 5;
    const int kh   = w >> 2;            // k half: chunks {2kh, 2kh+1}
    const int mpos = w & 1;             // m32 tile
    const int npos = (w >> 1) & 1;      // n16 tile
    const int wmB  = mpos * 32;
    const int wnB  = npos * 16;

    const uint32_t mb0 = sb + SM_MB;
    if (tid == 0) {
        for (int c = 0; c < 5; c++) mbar_init(mb0 + c * 8, 1);
        asm volatile("fence.proxy.async.shared::cta;" ::: "memory");
        mbar_expect_tx(mb0 + 32, (uint32_t)WSLAB);
        bulk_g2s(sb + SM_W, g_Wr + (size_t)(dir * 64 + blk) * WSLAB, (uint32_t)WSLAB, mb0 + 32);
    }
    __syncthreads();
    mbar_wait(mb0 + 32, 0);

    const uint32_t aRowB = (uint32_t)(wmB + (lane & 15));
    const uint32_t aByte = (lane & 16) ? 16u : 0u;
    const uint32_t bRow  = (uint32_t)(wnB + (lane & 7) + ((lane & 16) ? 8 : 0));
    const uint32_t bByte = (lane & 8) ? 16u : 0u;

    const float* xprjD = g_xproj + (size_t)dir * MM * FOURH;
    const char* hbase = g_hA + (size_t)dir * 2 * HA_SZ;
    unsigned* mycnt = &g_cnt[dir][blk >> 4];      // counter this block increments
    unsigned* spincnt = &g_cnt[dir][w & 3];       // counter warp w (<4) spins on

    // cell identity (used by kh0 warps)
    const int rA     = wmB + (lane >> 2);                 // fragment row base (mi adds 16)
    const int colp   = wnB + (lane & 3) * 2;              // fragment col base (ni adds 8)
    const int hhBase = npos * 4 + ((lane >> 1) & 1);      // hh for (ni=0); ni adds 2
    const int chunkW = blk >> 4;
    const uint32_t klocByte = (uint32_t)((blk & 15) * 16);
    float cst[2][2] = {{0.f, 0.f}, {0.f, 0.f}};

    for (int t = 0; t < TT; t++) {
        const int tt = dir ? (TT - 1 - t) : t;

        // Per-chunk acquire + copy: warp c (c<4) lane 0 handles chunk c
        if (w < 4 && lane == 0) {
            unsigned target = 16u * (unsigned)t;
            unsigned v;
            do {
                asm volatile("ld.acquire.gpu.u32 %0, [%1];" : "=r"(v) : "l"(spincnt) : "memory");
            } while (v < target);
            asm volatile("fence.proxy.async.shared::cta;" ::: "memory");
            const char* src = hbase + (size_t)(t & 1) * HA_SZ + (size_t)w * CH_SZ;
            mbar_expect_tx(mb0 + w * 8, (uint32_t)CH_SZ);
            bulk_g2s(sb + SM_A + (uint32_t)w * CH_SZ, src, (uint32_t)CH_SZ, mb0 + w * 8);
        }

        // kh0 warps prefetch xproj addends + masks (hidden behind MMA)
        float2 xg[2][2][2];    // [mi][ni][rowhalf]
        float mreg[2];
        if (kh == 0) {
            const float* base = xprjD + (size_t)tt * BB * FOURH + blk * 32;
#pragma unroll
            for (int mi = 0; mi < 2; mi++) {
                int r = rA + mi * 16;
#pragma unroll
                for (int ni = 0; ni < 2; ni++) {
                    xg[mi][ni][0] = *(const float2*)&base[(size_t)r * FOURH + colp + ni * 8];
                    xg[mi][ni][1] = *(const float2*)&base[(size_t)(r + 8) * FOURH + colp + ni * 8];
                }
                mreg[mi] = (float)mask[(rA + mi * 16 + ((lane & 1) << 3)) * TT + tt];
            }
        }

        // MMA over this warp's K-half: 4 chains x 48 links
        float cf[2][2][4];     // [mi][ni][4]
#pragma unroll
        for (int mi = 0; mi < 2; mi++)
#pragma unroll
            for (int ni = 0; ni < 2; ni++)
#pragma unroll
                for (int j = 0; j < 4; j++) cf[mi][ni][j] = 0.f;

        const uint32_t par = (uint32_t)(t & 1);
#pragma unroll
        for (int cc = 0; cc < 2; cc++) {
            int c = kh * 2 + cc;
            mbar_wait(mb0 + c * 8, par);
            uint32_t baseA = sb + SM_A + (uint32_t)c * CH_SZ;
#pragma unroll
            for (int ks = 0; ks < 8; ks++) {
                uint32_t ah[2][4], al[2][4], bh[4], bl[4];
#pragma unroll
                for (int mi = 0; mi < 2; mi++) {
                    uint32_t ra = (aRowB + (uint32_t)mi * 16) * 272 + (uint32_t)ks * 32 + aByte;
                    ldm_x4(ah[mi][0], ah[mi][1], ah[mi][2], ah[mi][3], baseA + ra);
                    ldm_x4(al[mi][0], al[mi][1], al[mi][2], al[mi][3], baseA + CH_HALF + ra);
                }
                uint32_t kb = ((uint32_t)(c * 8 + ks)) * 32 + bByte;
                uint32_t rb = sb + SM_W + bRow * 1040 + kb;
                ldm_x4(bh[0], bh[1], bh[2], bh[3], rb);
                ldm_x4(bl[0], bl[1], bl[2], bl[3], rb + WLO);
#pragma unroll
                for (int mi = 0; mi < 2; mi++)
#pragma unroll
                    for (int ni = 0; ni < 2; ni++) {
                        int o = ni * 2;
                        MMA_BF16(cf[mi][ni], ah[mi], bh[o], bh[o + 1]);
                        MMA_BF16(cf[mi][ni], ah[mi], bl[o], bl[o + 1]);
                        MMA_BF16(cf[mi][ni], al[mi], bh[o], bh[o + 1]);
                    }
            }
        }

        // kh1 warps dump partials: sRed[((w-4)*16 + frag)*32 + lane]
        if (kh == 1) {
            float* dst = sRed + (size_t)(w - 4) * 512 + lane;
#pragma unroll
            for (int mi = 0; mi < 2; mi++)
#pragma unroll
                for (int ni = 0; ni < 2; ni++)
#pragma unroll
                    for (int j = 0; j < 4; j++)
                        dst[((mi * 2 + ni) * 4 + j) * 32] = cf[mi][ni][j];
        }
        __syncthreads();   // sync1: partials staged

        // kh0 warps: reduce, add xproj, cells, stage h
        if (kh == 0) {
            const float* src = sRed + (size_t)w * 512 + lane;
#pragma unroll
            for (int mi = 0; mi < 2; mi++)
#pragma unroll
                for (int ni = 0; ni < 2; ni++) {
#pragma unroll
                    for (int j = 0; j < 4; j++)
                        cf[mi][ni][j] += src[((mi * 2 + ni) * 4 + j) * 32];

                    cf[mi][ni][0] += xg[mi][ni][0].x;  cf[mi][ni][1] += xg[mi][ni][0].y;
                    cf[mi][ni][2] += xg[mi][ni][1].x;  cf[mi][ni][3] += xg[mi][ni][1].y;

                    float sx = (lane & 1) ? cf[mi][ni][0] : cf[mi][ni][2];
                    float sy = (lane & 1) ? cf[mi][ni][1] : cf[mi][ni][3];
                    float rx = __shfl_xor_sync(0xffffffffu, sx, 1);
                    float ry = __shfl_xor_sync(0xffffffffu, sy, 1);

                    float gi, gf, gg, go;
                    if (!(lane & 1)) { gi = cf[mi][ni][0]; gf = cf[mi][ni][1]; gg = rx; go = ry; }
                    else             { gi = rx;            gf = ry;            gg = cf[mi][ni][2]; go = cf[mi][ni][3]; }

                    float si = sig_(gi);
                    float sf = sig_(gf);
                    float so = sig_(go);
                    float tg = 2.f * sig_(2.f * gg) - 1.f;
                    float c2 = sf * cst[mi][ni] + si * tg;
                    float tc = 2.f * sig_(2.f * c2) - 1.f;
                    float hn = so * tc * mreg[mi];
                    cst[mi][ni] = c2 * mreg[mi];

                    int b_cell = rA + mi * 16 + ((lane & 1) << 3);
                    int hh = hhBase + ni * 2;
                    __nv_bfloat16 hb = __float2bfloat16(hn);
                    __nv_bfloat16 lb = __float2bfloat16(hn - __bfloat162float(hb));
                    sHhi[b_cell * 8 + hh] = __bfloat16_as_ushort(hb);
                    sHlo[b_cell * 8 + hh] = __bfloat16_as_ushort(lb);
                    if (mode) sF32[b_cell * 8 + hh] = hn;
                }
        }
        __syncthreads();   // sync2: h staged

        // Stores: h state (tid<128), aux outputs (tid>=128)
        char* hout = (char*)(hbase + (size_t)((t + 1) & 1) * HA_SZ + (size_t)chunkW * CH_SZ);
        if (tid < 64) {
            uint4 v = *(uint4*)((char*)sHhi + tid * 16);
            *(uint4*)(hout + tid * 272 + klocByte) = v;
        } else if (tid < 128) {
            int r = tid - 64;
            uint4 v = *(uint4*)((char*)sHlo + r * 16);
            *(uint4*)(hout + CH_HALF + r * 272 + klocByte) = v;
        } else if (mode == 0) {
            if (tid < 192) {
                int r = tid - 128;
                uint4 v = *(uint4*)((char*)sHhi + r * 16);
                *(uint4*)((char*)g_Ahi + ((size_t)(tt * 64 + r) * 1024 + dir * 512 + blk * 8) * 2) = v;
            } else {
                int r = tid - 192;
                uint4 v = *(uint4*)((char*)sHlo + r * 16);
                *(uint4*)((char*)g_Alo + ((size_t)(tt * 64 + r) * 1024 + dir * 512 + blk * 8) * 2) = v;
            }
        } else {
            int r = (tid - 128) >> 1, half = tid & 1;
            float4 v = *(float4*)((char*)sF32 + r * 32 + half * 16);
            *(float4*)&outp[((size_t)tt * 64 + r) * 1024 + dir * 512 + blk * 8 + half * 4] = v;
        }

        __syncthreads();   // sync3: stores issued; guards mbar re-arm + sRed reuse
        if (tid == 0) {
            asm volatile("red.release.gpu.global.add.u32 [%0], %1;" :: "l"(mycnt), "r"(1u) : "memory");
        }
    }
}

// ---------------------------------------------------------------------------
// kernel_launch
// ---------------------------------------------------------------------------
extern "C" void kernel_launch(void* const* d_in, const int* in_sizes, int n_in,
                              void* d_out, int out_size)
{
    const float* x    = (const float*)d_in[0];
    const int*   mask = (const int*)  d_in[1];
    const float* w_ih = (const float*)d_in[2];
    const float* w_hh = (const float*)d_in[3];
    const float* b_ih = (const float*)d_in[4];
    const float* b_hh = (const float*)d_in[5];
    float* out = (float*)d_out;

    __nv_bfloat16 *pAh, *pAl, *pWh, *pWl;
    cudaGetSymbolAddress((void**)&pAh, g_Ahi);
    cudaGetSymbolAddress((void**)&pAl, g_Alo);
    cudaGetSymbolAddress((void**)&pWh, g_Whi);
    cudaGetSymbolAddress((void**)&pWl, g_Wlo);

    cudaFuncSetAttribute(lstm_mma,
                         cudaFuncAttributeMaxDynamicSharedMemorySize, SMEM_LSTM);
    cudaFuncSetAttribute(proj_mma,
                         cudaFuncAttributeMaxDynamicSharedMemorySize, SMEM_PROJ);

    dim3 gproj(128, 32);
    dim3 gpers(64, 2);

    for (int layer = 0; layer < 2; layer++) {
        if (layer == 0) pack_bf16<<<8192, 256>>>(x, pAh, pAl);

        pack_bf16<<<2048, 256>>>(w_ih + (size_t)layer * 2 * FOURH * KP, pWh, pWl);
        pack_Wr<<<128, 256>>>(w_hh + (size_t)layer * 2 * FOURH * HH);
        zero_state<<<136, 256>>>();

        proj_mma<<<gproj, 256, SMEM_PROJ>>>(
            pAh, pAl, pWh, pWl,
            b_ih + (size_t)layer * 2 * FOURH,
            b_hh + (size_t)layer * 2 * FOURH);

        lstm_mma<<<gpers, 256, SMEM_LSTM>>>(mask, (layer == 1) ? out : nullptr, layer);
    }
}

// round 11
// speedup vs baseline: 1.2557x; 1.2557x over previous
#include <cuda_runtime.h>
#include <cuda_fp16.h>
#include <math.h>
#include <stdint.h>

// Problem constants
#define TT     256
#define BB     64
#define HH     512
#define FOURH  2048
#define KP     1024
#define MM     (TT*BB)     // 16384

// ---------------------------------------------------------------------------
// Device scratch (static only)
// ---------------------------------------------------------------------------
__device__ float g_xproj[(size_t)2*MM*FOURH];        // input projections, pr-packed cols
__device__ unsigned g_cnt[2][4];                     // per (dir, chunk) producer counters

// proj operands: fp16. A split hi/lo; W hi only. Layer-1 A written by lstm_mma.
__device__ __align__(16) __half g_Ahi[(size_t)MM*KP];
__device__ __align__(16) __half g_Alo[(size_t)MM*KP];
__device__ __align__(16) __half g_Whi[(size_t)4096*KP];

// recurrence W_hh: per (dir, block) slab: hi[32][1040B] (fp16, no lo)
#define WSLAB 33280
__device__ __align__(128) char g_Wr[(size_t)2*64*WSLAB];

// recurrence h state: [dir][ping][chunk4]{ hi[64][272B], lo[64][272B] } (fp16)
#define CH_HALF 17408
#define CH_SZ   34816
#define HA_SZ   (4*CH_SZ)    // 139264 per (dir,ping)
__device__ __align__(128) char g_hA[(size_t)2*2*HA_SZ];

// ---------------------------------------------------------------------------
// PTX helpers
// ---------------------------------------------------------------------------
__device__ __forceinline__ uint32_t smem_u32(const void* p) {
    uint32_t a;
    asm("{ .reg .u64 t; cvta.to.shared.u64 t, %1; cvt.u32.u64 %0, t; }" : "=r"(a) : "l"(p));
    return a;
}
__device__ __forceinline__ void mbar_init(uint32_t mb, uint32_t cnt) {
    asm volatile("mbarrier.init.shared.b64 [%0], %1;" :: "r"(mb), "r"(cnt) : "memory");
}
__device__ __forceinline__ void mbar_expect_tx(uint32_t mb, uint32_t bytes) {
    asm volatile("mbarrier.arrive.expect_tx.shared.b64 _, [%0], %1;" :: "r"(mb), "r"(bytes) : "memory");
}
__device__ __forceinline__ void bulk_g2s(uint32_t dst, const void* src, uint32_t bytes, uint32_t mb) {
    asm volatile("cp.async.bulk.shared::cta.global.mbarrier::complete_tx::bytes [%0], [%1], %2, [%3];"
                 :: "r"(dst), "l"(src), "r"(bytes), "r"(mb) : "memory");
}
__device__ __forceinline__ void mbar_wait(uint32_t mb, uint32_t parity) {
    uint32_t done;
    asm volatile("{\n\t.reg .pred p;\n\t"
        "mbarrier.try_wait.parity.acquire.cta.shared::cta.b64 p, [%1], %2;\n\t"
        "selp.b32 %0, 1, 0, p;\n\t}"
        : "=r"(done) : "r"(mb), "r"(parity) : "memory");
    while (!done) {
        asm volatile("{\n\t.reg .pred p;\n\t"
            "mbarrier.try_wait.parity.acquire.cta.shared::cta.b64 p, [%1], %2, 0x989680;\n\t"
            "selp.b32 %0, 1, 0, p;\n\t}"
            : "=r"(done) : "r"(mb), "r"(parity) : "memory");
    }
}
__device__ __forceinline__ void cpa16(uint32_t dst, const void* src) {
    asm volatile("cp.async.cg.shared.global [%0], [%1], 16;" :: "r"(dst), "l"(src) : "memory");
}
__device__ __forceinline__ void ldm_x4(uint32_t& r0, uint32_t& r1, uint32_t& r2, uint32_t& r3,
                                       uint32_t addr) {
    asm volatile("ldmatrix.sync.aligned.m8n8.x4.shared.b16 {%0,%1,%2,%3}, [%4];"
                 : "=r"(r0), "=r"(r1), "=r"(r2), "=r"(r3) : "r"(addr));
}
#define MMA_F16(c, a, b0v, b1v) \
    asm volatile("mma.sync.aligned.m16n8k16.row.col.f32.f16.f16.f32 " \
        "{%0,%1,%2,%3}, {%4,%5,%6,%7}, {%8,%9}, {%0,%1,%2,%3};" \
        : "+f"((c)[0]), "+f"((c)[1]), "+f"((c)[2]), "+f"((c)[3]) \
        : "r"((a)[0]), "r"((a)[1]), "r"((a)[2]), "r"((a)[3]), "r"(b0v), "r"(b1v))

__device__ __forceinline__ float sig_(float x) {
    return __fdividef(1.f, 1.f + __expf(-x));
}
// fp16 hi/lo split pack of a float pair
__device__ __forceinline__ uint32_t pack_hilo16(float a, float b, uint32_t& lo) {
    __half h0 = __float2half_rn(a);
    __half h1 = __float2half_rn(b);
    __half l0 = __float2half_rn(a - __half2float(h0));
    __half l1 = __float2half_rn(b - __half2float(h1));
    lo = (uint32_t)__half_as_ushort(l0) | ((uint32_t)__half_as_ushort(l1) << 16);
    return (uint32_t)__half_as_ushort(h0) | ((uint32_t)__half_as_ushort(h1) << 16);
}

// ---------------------------------------------------------------------------
// Zero h slot 0 (both dirs) + producer counters
// ---------------------------------------------------------------------------
__global__ void zero_state() {
    uint32_t i = blockIdx.x * 256 + threadIdx.x;
    float* p = (float*)g_hA;
    if (i < HA_SZ / 4) {
        p[i] = 0.f;
        p[i + (2 * HA_SZ) / 4] = 0.f;
    }
    if (i < 8) ((unsigned*)g_cnt)[i] = 0u;
}

// ---------------------------------------------------------------------------
// Pack fp32 -> hi/lo fp16 (A operand), 8 elems/thread
// ---------------------------------------------------------------------------
__global__ __launch_bounds__(256) void pack_f16_split(
    const float* __restrict__ src,
    __half* __restrict__ hi, __half* __restrict__ lo)
{
    size_t i = ((size_t)blockIdx.x * 256 + threadIdx.x) * 8;
    float4 v0 = *(const float4*)(src + i);
    float4 v1 = *(const float4*)(src + i + 4);
    float xv[8] = {v0.x, v0.y, v0.z, v0.w, v1.x, v1.y, v1.z, v1.w};
    uint32_t hp[4], lp[4];
#pragma unroll
    for (int e = 0; e < 4; e++) hp[e] = pack_hilo16(xv[2*e], xv[2*e+1], lp[e]);
    *(uint4*)(hi + i) = make_uint4(hp[0], hp[1], hp[2], hp[3]);
    *(uint4*)(lo + i) = make_uint4(lp[0], lp[1], lp[2], lp[3]);
}

// ---------------------------------------------------------------------------
// Pack fp32 -> single fp16 (W operand), 8 elems/thread
// ---------------------------------------------------------------------------
__global__ __launch_bounds__(256) void pack_f16_single(
    const float* __restrict__ src, __half* __restrict__ hi)
{
    size_t i = ((size_t)blockIdx.x * 256 + threadIdx.x) * 8;
    float4 v0 = *(const float4*)(src + i);
    float4 v1 = *(const float4*)(src + i + 4);
    float xv[8] = {v0.x, v0.y, v0.z, v0.w, v1.x, v1.y, v1.z, v1.w};
    uint32_t hp[4];
#pragma unroll
    for (int e = 0; e < 4; e++) {
        __half h0 = __float2half_rn(xv[2*e]);
        __half h1 = __float2half_rn(xv[2*e+1]);
        hp[e] = (uint32_t)__half_as_ushort(h0) | ((uint32_t)__half_as_ushort(h1) << 16);
    }
    *(uint4*)(hi + i) = make_uint4(hp[0], hp[1], hp[2], hp[3]);
}

// ---------------------------------------------------------------------------
// Pack W_hh into per-block slabs (fp16 hi only): row pr=hh*4+g
// ---------------------------------------------------------------------------
__global__ __launch_bounds__(256) void pack_Wr(const float* __restrict__ whh) {
    const int dir = blockIdx.x >> 6, blk = blockIdx.x & 63;
    char* slab = g_Wr + (size_t)(dir * 64 + blk) * WSLAB;
    for (int i = threadIdx.x; i < 8192; i += 256) {
        int r = i >> 8;
        int k2 = (i & 255) * 2;
        int hh = r >> 2, g = r & 3;
        int grow = g * HH + blk * 8 + hh;
        float2 v = *(const float2*)&whh[((size_t)dir * FOURH + grow) * HH + k2];
        __half h0 = __float2half_rn(v.x);
        __half h1 = __float2half_rn(v.y);
        *(uint32_t*)(slab + r * 1040 + k2 * 2) =
            (uint32_t)__half_as_ushort(h0) | ((uint32_t)__half_as_ushort(h1) << 16);
    }
}

// ---------------------------------------------------------------------------
// HMMA fp16 projection GEMM, 3-stage pipeline, tile 128m x 128pr x 64k.
// Stage = { Ahi, Alo, Whi } 3 tiles. 2 MMA products per fragment.
// pr = hh*4+g; W natural row for pr: n = (pr&3)*512 + (pr>>2).
// ---------------------------------------------------------------------------
#define ROWB   144
#define TILEB  (128*ROWB)                 // 18432
#define STGB   (3*TILEB)                  // 55296
#define OFF_BIAS (3*STGB)                 // 165888
#define SMEM_PROJ (OFF_BIAS + 768)

__global__ __launch_bounds__(256, 1) void proj_mma(
    const __half* __restrict__ Ah, const __half* __restrict__ Al,
    const __half* __restrict__ Wh,
    const float* __restrict__ b1, const float* __restrict__ b2)
{
    extern __shared__ __align__(128) char smp[];
    const uint32_t sb = smem_u32(smp);
    float* bias = (float*)(smp + OFF_BIAS);

    const int tid  = threadIdx.x;
    const int lane = tid & 31;
    const int w    = tid >> 5;
    const int m0   = blockIdx.x * 128;
    const int dir  = blockIdx.y >> 4;
    const int prG  = (blockIdx.y & 15) * 128;
    const int prB  = prG >> 2;
    const int wm   = (w >> 2) * 64;
    const int wn   = (w & 3) * 32;

    if (tid < 128) {
        int n = (tid & 3) * 512 + prB + (tid >> 2);
        bias[tid] = b1[dir * FOURH + n] + b2[dir * FOURH + n];
    }

    // 3 tiles x 128 rows x 8 col-groups = 3072 chunks; 12 per thread
    int cr[12], cc[12], ct[12];
#pragma unroll
    for (int i = 0; i < 12; i++) {
        int c = i * 256 + tid;
        ct[i] = c >> 10; cr[i] = (c >> 3) & 127; cc[i] = c & 7;
    }

    auto load_stage = [&](int s, int kt) {
        uint32_t base = sb + (uint32_t)s * STGB;
#pragma unroll
        for (int i = 0; i < 12; i++) {
            uint32_t dst = base + (uint32_t)ct[i] * TILEB + (uint32_t)cr[i] * ROWB + (uint32_t)cc[i] * 16;
            const __half* g;
            if (ct[i] == 0)      g = Ah + (size_t)(m0 + cr[i]) * KP + kt * 64 + cc[i] * 8;
            else if (ct[i] == 1) g = Al + (size_t)(m0 + cr[i]) * KP + kt * 64 + cc[i] * 8;
            else {
                int n = (cr[i] & 3) * 512 + prB + (cr[i] >> 2);
                g = Wh + (size_t)(dir * FOURH + n) * KP + kt * 64 + cc[i] * 8;
            }
            cpa16(dst, g);
        }
        asm volatile("cp.async.commit_group;" ::: "memory");
    };

    float c[4][4][4];
#pragma unroll
    for (int mi = 0; mi < 4; mi++)
#pragma unroll
        for (int ni = 0; ni < 4; ni++)
#pragma unroll
            for (int j = 0; j < 4; j++) c[mi][ni][j] = 0.f;

    const uint32_t aRow  = (uint32_t)(wm + (lane & 15));
    const uint32_t aByte = (lane & 16) ? 16u : 0u;
    const uint32_t bRow  = (uint32_t)(wn + (lane & 7) + ((lane & 16) ? 8 : 0));
    const uint32_t bByte = (lane & 8) ? 16u : 0u;

    load_stage(0, 0);
    load_stage(1, 1);

    for (int kt = 0; kt < 16; kt++) {
        if (kt + 2 < 16) {
            load_stage((kt + 2) % 3, kt + 2);
            asm volatile("cp.async.wait_group 2;" ::: "memory");
        } else if (kt + 1 < 16) {
            asm volatile("cp.async.wait_group 1;" ::: "memory");
        } else {
            asm volatile("cp.async.wait_group 0;" ::: "memory");
        }
        __syncthreads();

        uint32_t st = sb + (uint32_t)(kt % 3) * STGB;
#pragma unroll
        for (int ks = 0; ks < 4; ks++) {
            uint32_t kb = (uint32_t)(ks * 32);
            uint32_t ah[4][4], al[4][4], bh[2][4];
#pragma unroll
            for (int mi = 0; mi < 4; mi++) {
                uint32_t ra = (aRow + mi * 16) * ROWB + kb + aByte;
                ldm_x4(ah[mi][0], ah[mi][1], ah[mi][2], ah[mi][3], st + ra);
                ldm_x4(al[mi][0], al[mi][1], al[mi][2], al[mi][3], st + TILEB + ra);
            }
#pragma unroll
            for (int np = 0; np < 2; np++) {
                uint32_t rb = (bRow + np * 16) * ROWB + kb + bByte;
                ldm_x4(bh[np][0], bh[np][1], bh[np][2], bh[np][3], st + 2 * TILEB + rb);
            }
#pragma unroll
            for (int mi = 0; mi < 4; mi++)
#pragma unroll
                for (int ni = 0; ni < 4; ni++) {
                    int np = ni >> 1, o = (ni & 1) * 2;
                    MMA_F16(c[mi][ni], ah[mi], bh[np][o], bh[np][o + 1]);
                    MMA_F16(c[mi][ni], al[mi], bh[np][o], bh[np][o + 1]);
                }
        }
        __syncthreads();
    }

    float* outD = g_xproj + (size_t)dir * MM * FOURH;
#pragma unroll
    for (int mi = 0; mi < 4; mi++) {
        int row0 = m0 + wm + mi * 16 + (lane >> 2);
#pragma unroll
        for (int ni = 0; ni < 4; ni++) {
            int colL = wn + ni * 8 + (lane & 3) * 2;
            float bx = bias[colL], by = bias[colL + 1];
            *(float2*)&outD[(size_t)row0 * FOURH + prG + colL] =
                make_float2(c[mi][ni][0] + bx, c[mi][ni][1] + by);
            *(float2*)&outD[(size_t)(row0 + 8) * FOURH + prG + colL] =
                make_float2(c[mi][ni][2] + bx, c[mi][ni][3] + by);
        }
    }
}

// ---------------------------------------------------------------------------
// Persistent HMMA fp16 recurrence (R9 structure). grid = (64 blk, 2 dir),
// 256 threads (8 warps: 4m x 2n of m16n16). h split hi/lo fp16, W single fp16.
// 2 MMA products per fragment. Per-chunk producer counters.
// ---------------------------------------------------------------------------
#define SM_A   0                        // 4 chunks x (hi 17408 + lo 17408)
#define SM_W   139264                   // hi[32][1040] = 33280
#define SM_ST  172544                   // staging: hi 1KB | lo 1KB | f32 2KB
#define SM_MB  176640                   // 5 mbarriers
#define SMEM_LSTM 176704

__global__ __launch_bounds__(256, 1) void lstm_mma(
    const int* __restrict__ mask,     // [B][T]
    float*     __restrict__ outp,     // [T][B][2H] (mode 1)
    int mode)
{
    extern __shared__ __align__(128) char sm[];
    const uint32_t sb = smem_u32(sm);
    uint16_t* sHhi = (uint16_t*)(sm + SM_ST);
    uint16_t* sHlo = (uint16_t*)(sm + SM_ST + 1024);
    float*    sF32 = (float*)(sm + SM_ST + 2048);

    const int dir = blockIdx.y;
    const int blk = blockIdx.x;
    const int tid = threadIdx.x;
    const int lane = tid & 31;
    const int w = tid >> 5;
    const int wm = (w >> 1) * 16;       // batch offset
    const int wn = (w & 1) * 16;        // pr offset

    const uint32_t mb0 = sb + SM_MB;
    if (tid == 0) {
        for (int c = 0; c < 5; c++) mbar_init(mb0 + c * 8, 1);
        asm volatile("fence.proxy.async.shared::cta;" ::: "memory");
        mbar_expect_tx(mb0 + 32, (uint32_t)WSLAB);
        bulk_g2s(sb + SM_W, g_Wr + (size_t)(dir * 64 + blk) * WSLAB, (uint32_t)WSLAB, mb0 + 32);
    }
    __syncthreads();
    mbar_wait(mb0 + 32, 0);

    const uint32_t aRow  = (uint32_t)(wm + (lane & 15));
    const uint32_t aByte = (lane & 16) ? 16u : 0u;
    const uint32_t bRow  = (uint32_t)(wn + (lane & 7) + ((lane & 16) ? 8 : 0));
    const uint32_t bByte = (lane & 8) ? 16u : 0u;

    const float* xprjD = g_xproj + (size_t)dir * MM * FOURH;
    const char* hbase = g_hA + (size_t)dir * 2 * HA_SZ;
    unsigned* mycnt = &g_cnt[dir][blk >> 4];      // counter this block increments
    unsigned* spincnt = &g_cnt[dir][w & 3];       // counter warp w (<4) spins on

    // cell identity
    const int r0    = wm + (lane >> 2);
    const int colp  = wn + (lane & 3) * 2;
    const int b_cell = r0 + ((lane & 1) << 3);
    const int hhA   = (wn >> 2) + ((lane >> 1) & 1);
    const int chunk = blk >> 4;
    const uint32_t klocByte = (uint32_t)((blk & 15) * 16);
    float cst[2] = {0.f, 0.f};

    for (int t = 0; t < TT; t++) {
        const int tt = dir ? (TT - 1 - t) : t;

        // Per-chunk acquire + copy: warp c (c<4) lane 0 handles chunk c
        if (w < 4 && lane == 0) {
            unsigned target = 16u * (unsigned)t;
            unsigned v;
            do {
                asm volatile("ld.acquire.gpu.u32 %0, [%1];" : "=r"(v) : "l"(spincnt) : "memory");
            } while (v < target);
            asm volatile("fence.proxy.async.shared::cta;" ::: "memory");
            const char* src = hbase + (size_t)(t & 1) * HA_SZ + (size_t)w * CH_SZ;
            mbar_expect_tx(mb0 + w * 8, (uint32_t)CH_SZ);
            bulk_g2s(sb + SM_A + (uint32_t)w * CH_SZ, src, (uint32_t)CH_SZ, mb0 + w * 8);
        }

        // Prefetch xproj fragment addends + mask
        float2 xg[2][2];
        {
            const float* base = xprjD + (size_t)tt * BB * FOURH + blk * 32;
#pragma unroll
            for (int ni = 0; ni < 2; ni++) {
                xg[ni][0] = *(const float2*)&base[(size_t)r0 * FOURH + colp + ni * 8];
                xg[ni][1] = *(const float2*)&base[(size_t)(r0 + 8) * FOURH + colp + ni * 8];
            }
        }
        const float mreg = (float)mask[b_cell * TT + tt];

        // MMA: C[64b x 32pr] = h[64x512] . Wslice^T (fp16, A-split 2 products)
        float cf[2][4];
#pragma unroll
        for (int ni = 0; ni < 2; ni++)
#pragma unroll
            for (int j = 0; j < 4; j++) cf[ni][j] = 0.f;

        const uint32_t par = (uint32_t)(t & 1);
#pragma unroll
        for (int c = 0; c < 4; c++) {
            mbar_wait(mb0 + c * 8, par);
            uint32_t baseA = sb + SM_A + (uint32_t)c * CH_SZ;
#pragma unroll
            for (int ks = 0; ks < 8; ks++) {
                uint32_t ah[4], al[4], bh[4];
                uint32_t ra = aRow * 272 + (uint32_t)ks * 32 + aByte;
                ldm_x4(ah[0], ah[1], ah[2], ah[3], baseA + ra);
                ldm_x4(al[0], al[1], al[2], al[3], baseA + CH_HALF + ra);
                uint32_t kb = ((uint32_t)(c * 8 + ks)) * 32 + bByte;
                ldm_x4(bh[0], bh[1], bh[2], bh[3], sb + SM_W + bRow * 1040 + kb);
#pragma unroll
                for (int ni = 0; ni < 2; ni++) {
                    int o = ni * 2;
                    MMA_F16(cf[ni], ah, bh[o], bh[o + 1]);
                    MMA_F16(cf[ni], al, bh[o], bh[o + 1]);
                }
            }
        }

        // Cells directly from fragments
#pragma unroll
        for (int ni = 0; ni < 2; ni++) {
            cf[ni][0] += xg[ni][0].x;  cf[ni][1] += xg[ni][0].y;
            cf[ni][2] += xg[ni][1].x;  cf[ni][3] += xg[ni][1].y;

            float sx = (lane & 1) ? cf[ni][0] : cf[ni][2];
            float sy = (lane & 1) ? cf[ni][1] : cf[ni][3];
            float rx = __shfl_xor_sync(0xffffffffu, sx, 1);
            float ry = __shfl_xor_sync(0xffffffffu, sy, 1);

            float gi, gf, gg, go;
            if (!(lane & 1)) { gi = cf[ni][0]; gf = cf[ni][1]; gg = rx; go = ry; }
            else             { gi = rx;        gf = ry;        gg = cf[ni][2]; go = cf[ni][3]; }

            float si = sig_(gi);
            float sf = sig_(gf);
            float so = sig_(go);
            float tg = 2.f * sig_(2.f * gg) - 1.f;
            float c2 = sf * cst[ni] + si * tg;
            float tc = 2.f * sig_(2.f * c2) - 1.f;
            float hn = so * tc * mreg;
            cst[ni] = c2 * mreg;

            int hh = hhA + ni * 2;
            __half hb = __float2half_rn(hn);
            __half lb = __float2half_rn(hn - __half2float(hb));
            sHhi[b_cell * 8 + hh] = __half_as_ushort(hb);
            sHlo[b_cell * 8 + hh] = __half_as_ushort(lb);
            if (mode) sF32[b_cell * 8 + hh] = hn;
        }
        __syncthreads();   // sync1: cells staged

        // Stores: h state (tid<128), aux outputs (tid>=128)
        char* hout = (char*)(hbase + (size_t)((t + 1) & 1) * HA_SZ + (size_t)chunk * CH_SZ);
        if (tid < 64) {
            uint4 v = *(uint4*)((char*)sHhi + tid * 16);
            *(uint4*)(hout + tid * 272 + klocByte) = v;
        } else if (tid < 128) {
            int r = tid - 64;
            uint4 v = *(uint4*)((char*)sHlo + r * 16);
            *(uint4*)(hout + CH_HALF + r * 272 + klocByte) = v;
        } else if (mode == 0) {
            if (tid < 192) {
                int r = tid - 128;
                uint4 v = *(uint4*)((char*)sHhi + r * 16);
                *(uint4*)((char*)g_Ahi + ((size_t)(tt * 64 + r) * 1024 + dir * 512 + blk * 8) * 2) = v;
            } else {
                int r = tid - 192;
                uint4 v = *(uint4*)((char*)sHlo + r * 16);
                *(uint4*)((char*)g_Alo + ((size_t)(tt * 64 + r) * 1024 + dir * 512 + blk * 8) * 2) = v;
            }
        } else {
            int r = (tid - 128) >> 1, half = tid & 1;
            float4 v = *(float4*)((char*)sF32 + r * 32 + half * 16);
            *(float4*)&outp[((size_t)tt * 64 + r) * 1024 + dir * 512 + blk * 8 + half * 4] = v;
        }

        __syncthreads();   // sync2: all stores issued; guards mbar re-arm
        if (tid == 0) {
            asm volatile("red.release.gpu.global.add.u32 [%0], %1;" :: "l"(mycnt), "r"(1u) : "memory");
        }
    }
}

// ---------------------------------------------------------------------------
// kernel_launch
// ---------------------------------------------------------------------------
extern "C" void kernel_launch(void* const* d_in, const int* in_sizes, int n_in,
                              void* d_out, int out_size)
{
    const float* x    = (const float*)d_in[0];
    const int*   mask = (const int*)  d_in[1];
    const float* w_ih = (const float*)d_in[2];
    const float* w_hh = (const float*)d_in[3];
    const float* b_ih = (const float*)d_in[4];
    const float* b_hh = (const float*)d_in[5];
    float* out = (float*)d_out;

    __half *pAh, *pAl, *pWh;
    cudaGetSymbolAddress((void**)&pAh, g_Ahi);
    cudaGetSymbolAddress((void**)&pAl, g_Alo);
    cudaGetSymbolAddress((void**)&pWh, g_Whi);

    cudaFuncSetAttribute(lstm_mma,
                         cudaFuncAttributeMaxDynamicSharedMemorySize, SMEM_LSTM);
    cudaFuncSetAttribute(proj_mma,
                         cudaFuncAttributeMaxDynamicSharedMemorySize, SMEM_PROJ);

    dim3 gproj(128, 32);
    dim3 gpers(64, 2);

    for (int layer = 0; layer < 2; layer++) {
        if (layer == 0) pack_f16_split<<<8192, 256>>>(x, pAh, pAl);
        // layer 1: g_Ahi/g_Alo already written by layer-0 lstm_mma

        pack_f16_single<<<2048, 256>>>(w_ih + (size_t)layer * 2 * FOURH * KP, pWh);
        pack_Wr<<<128, 256>>>(w_hh + (size_t)layer * 2 * FOURH * HH);
        zero_state<<<136, 256>>>();

        proj_mma<<<gproj, 256, SMEM_PROJ>>>(
            pAh, pAl, pWh,
            b_ih + (size_t)layer * 2 * FOURH,
            b_hh + (size_t)layer * 2 * FOURH);

        lstm_mma<<<gpers, 256, SMEM_LSTM>>>(mask, (layer == 1) ? out : nullptr, layer);
    }
}

// round 12
// speedup vs baseline: 1.3247x; 1.0549x over previous
#include <cuda_runtime.h>
#include <cuda_fp16.h>
#include <math.h>
#include <stdint.h>

// Problem constants
#define TT     256
#define BB     64
#define HH     512
#define FOURH  2048
#define KP     1024
#define MM     (TT*BB)     // 16384

// ---------------------------------------------------------------------------
// Device scratch (static only)
// ---------------------------------------------------------------------------
__device__ float g_xproj[(size_t)2*MM*FOURH];        // input projections, pr-packed cols
__device__ unsigned g_cnt[2][4];                     // per (dir, chunk) producer counters

// proj operands: fp16. A split hi/lo; W hi only. Layer-1 A written by lstm_mma.
__device__ __align__(16) __half g_Ahi[(size_t)MM*KP];
__device__ __align__(16) __half g_Alo[(size_t)MM*KP];
__device__ __align__(16) __half g_Whi[(size_t)4096*KP];

// recurrence W_hh: per (dir, block) slab: hi[32][1040B] (fp16, no lo)
#define WSLAB 33280
__device__ __align__(128) char g_Wr[(size_t)2*64*WSLAB];

// recurrence h state: [dir][ping][chunk4]{ hi[64][272B], lo[64][272B] } (fp16)
#define CH_HALF 17408
#define CH_SZ   34816
#define HA_SZ   (4*CH_SZ)    // 139264 per (dir,ping)
__device__ __align__(128) char g_hA[(size_t)2*2*HA_SZ];

// ---------------------------------------------------------------------------
// PTX helpers
// ---------------------------------------------------------------------------
__device__ __forceinline__ uint32_t smem_u32(const void* p) {
    uint32_t a;
    asm("{ .reg .u64 t; cvta.to.shared.u64 t, %1; cvt.u32.u64 %0, t; }" : "=r"(a) : "l"(p));
    return a;
}
__device__ __forceinline__ void mbar_init(uint32_t mb, uint32_t cnt) {
    asm volatile("mbarrier.init.shared.b64 [%0], %1;" :: "r"(mb), "r"(cnt) : "memory");
}
__device__ __forceinline__ void mbar_expect_tx(uint32_t mb, uint32_t bytes) {
    asm volatile("mbarrier.arrive.expect_tx.shared.b64 _, [%0], %1;" :: "r"(mb), "r"(bytes) : "memory");
}
__device__ __forceinline__ void bulk_g2s(uint32_t dst, const void* src, uint32_t bytes, uint32_t mb) {
    asm volatile("cp.async.bulk.shared::cta.global.mbarrier::complete_tx::bytes [%0], [%1], %2, [%3];"
                 :: "r"(dst), "l"(src), "r"(bytes), "r"(mb) : "memory");
}
__device__ __forceinline__ void mbar_wait(uint32_t mb, uint32_t parity) {
    uint32_t done;
    asm volatile("{\n\t.reg .pred p;\n\t"
        "mbarrier.try_wait.parity.acquire.cta.shared::cta.b64 p, [%1], %2;\n\t"
        "selp.b32 %0, 1, 0, p;\n\t}"
        : "=r"(done) : "r"(mb), "r"(parity) : "memory");
    while (!done) {
        asm volatile("{\n\t.reg .pred p;\n\t"
            "mbarrier.try_wait.parity.acquire.cta.shared::cta.b64 p, [%1], %2, 0x989680;\n\t"
            "selp.b32 %0, 1, 0, p;\n\t}"
            : "=r"(done) : "r"(mb), "r"(parity) : "memory");
    }
}
__device__ __forceinline__ void cpa16(uint32_t dst, const void* src) {
    asm volatile("cp.async.cg.shared.global [%0], [%1], 16;" :: "r"(dst), "l"(src) : "memory");
}
__device__ __forceinline__ void ldm_x4(uint32_t& r0, uint32_t& r1, uint32_t& r2, uint32_t& r3,
                                       uint32_t addr) {
    asm volatile("ldmatrix.sync.aligned.m8n8.x4.shared.b16 {%0,%1,%2,%3}, [%4];"
                 : "=r"(r0), "=r"(r1), "=r"(r2), "=r"(r3) : "r"(addr));
}
#define MMA_F16(c, a, b0v, b1v) \
    asm volatile("mma.sync.aligned.m16n8k16.row.col.f32.f16.f16.f32 " \
        "{%0,%1,%2,%3}, {%4,%5,%6,%7}, {%8,%9}, {%0,%1,%2,%3};" \
        : "+f"((c)[0]), "+f"((c)[1]), "+f"((c)[2]), "+f"((c)[3]) \
        : "r"((a)[0]), "r"((a)[1]), "r"((a)[2]), "r"((a)[3]), "r"(b0v), "r"(b1v))

__device__ __forceinline__ float sig_(float x) {
    return __fdividef(1.f, 1.f + __expf(-x));
}
__device__ __forceinline__ uint32_t pack_hilo16(float a, float b, uint32_t& lo) {
    __half h0 = __float2half_rn(a);
    __half h1 = __float2half_rn(b);
    __half l0 = __float2half_rn(a - __half2float(h0));
    __half l1 = __float2half_rn(b - __half2float(h1));
    lo = (uint32_t)__half_as_ushort(l0) | ((uint32_t)__half_as_ushort(l1) << 16);
    return (uint32_t)__half_as_ushort(h0) | ((uint32_t)__half_as_ushort(h1) << 16);
}

// ---------------------------------------------------------------------------
// Pack fp32 -> hi/lo fp16 (A operand), 8 elems/thread
// ---------------------------------------------------------------------------
__global__ __launch_bounds__(256) void pack_f16_split(
    const float* __restrict__ src,
    __half* __restrict__ hi, __half* __restrict__ lo)
{
    size_t i = ((size_t)blockIdx.x * 256 + threadIdx.x) * 8;
    float4 v0 = *(const float4*)(src + i);
    float4 v1 = *(const float4*)(src + i + 4);
    float xv[8] = {v0.x, v0.y, v0.z, v0.w, v1.x, v1.y, v1.z, v1.w};
    uint32_t hp[4], lp[4];
#pragma unroll
    for (int e = 0; e < 4; e++) hp[e] = pack_hilo16(xv[2*e], xv[2*e+1], lp[e]);
    *(uint4*)(hi + i) = make_uint4(hp[0], hp[1], hp[2], hp[3]);
    *(uint4*)(lo + i) = make_uint4(lp[0], lp[1], lp[2], lp[3]);
}

// ---------------------------------------------------------------------------
// Pack fp32 -> single fp16 (W operand), 8 elems/thread
// ---------------------------------------------------------------------------
__global__ __launch_bounds__(256) void pack_f16_single(
    const float* __restrict__ src, __half* __restrict__ hi)
{
    size_t i = ((size_t)blockIdx.x * 256 + threadIdx.x) * 8;
    float4 v0 = *(const float4*)(src + i);
    float4 v1 = *(const float4*)(src + i + 4);
    float xv[8] = {v0.x, v0.y, v0.z, v0.w, v1.x, v1.y, v1.z, v1.w};
    uint32_t hp[4];
#pragma unroll
    for (int e = 0; e < 4; e++) {
        __half h0 = __float2half_rn(xv[2*e]);
        __half h1 = __float2half_rn(xv[2*e+1]);
        hp[e] = (uint32_t)__half_as_ushort(h0) | ((uint32_t)__half_as_ushort(h1) << 16);
    }
    *(uint4*)(hi + i) = make_uint4(hp[0], hp[1], hp[2], hp[3]);
}

// ---------------------------------------------------------------------------
// Pack W_hh into per-block slabs (fp16 hi only): row pr=hh*4+g.
// Also zeros h slot 0 (both dirs) + producer counters (fused zero_state).
// grid = 128
// ---------------------------------------------------------------------------
__global__ __launch_bounds__(256) void pack_Wr(const float* __restrict__ whh) {
    const int dir = blockIdx.x >> 6, blk = blockIdx.x & 63;
    char* slab = g_Wr + (size_t)(dir * 64 + blk) * WSLAB;
    for (int i = threadIdx.x; i < 8192; i += 256) {
        int r = i >> 8;
        int k2 = (i & 255) * 2;
        int hh = r >> 2, g = r & 3;
        int grow = g * HH + blk * 8 + hh;
        float2 v = *(const float2*)&whh[((size_t)dir * FOURH + grow) * HH + k2];
        __half h0 = __float2half_rn(v.x);
        __half h1 = __float2half_rn(v.y);
        *(uint32_t*)(slab + r * 1040 + k2 * 2) =
            (uint32_t)__half_as_ushort(h0) | ((uint32_t)__half_as_ushort(h1) << 16);
    }
    // fused zero_state: 128 blocks x 256 threads = 32768 threads
    uint32_t gid = blockIdx.x * 256 + threadIdx.x;
    float* p = (float*)g_hA;
    for (uint32_t i = gid; i < HA_SZ / 4; i += 32768) {
        p[i] = 0.f;                       // dir0 ping0
        p[i + (2 * HA_SZ) / 4] = 0.f;     // dir1 ping0
    }
    if (gid < 8) ((unsigned*)g_cnt)[gid] = 0u;
}

// ---------------------------------------------------------------------------
// HMMA fp16 projection GEMM, 3-stage pipeline, CTA tile 128m x 256pr x 64k.
// 8 warps = 2m x 4n, warp tile 64m x 64pr (mi 4 x ni 8 of m16n8), B in 4
// np-slices to bound live registers. Stage = { Ahi 18432 | Alo 18432 | W 36864 }.
// pr = hh*4+g; W natural row for pr: n = (pr&3)*512 + (pr>>2).
// ---------------------------------------------------------------------------
#define ROWB   144
#define TILEB  (128*ROWB)                 // 18432
#define WTILEB (256*ROWB)                 // 36864
#define STGB   (2*TILEB + WTILEB)         // 73728
#define OFF_BIAS (3*STGB)                 // 221184
#define SMEM_PROJ (OFF_BIAS + 1088)

__global__ __launch_bounds__(256, 1) void proj_mma(
    const __half* __restrict__ Ah, const __half* __restrict__ Al,
    const __half* __restrict__ Wh,
    const float* __restrict__ b1, const float* __restrict__ b2)
{
    extern __shared__ __align__(128) char smp[];
    const uint32_t sb = smem_u32(smp);
    float* bias = (float*)(smp + OFF_BIAS);

    const int tid  = threadIdx.x;
    const int lane = tid & 31;
    const int w    = tid >> 5;
    const int m0   = blockIdx.x * 128;
    const int dir  = blockIdx.y >> 3;
    const int prG  = (blockIdx.y & 7) * 256;    // pr-block base within dir
    const int prB  = prG >> 2;
    const int wm   = (w >> 2) * 64;
    const int wn   = (w & 3) * 64;

    {   // bias for all 256 pr columns
        int n = (tid & 3) * 512 + prB + (tid >> 2);
        bias[tid] = b1[dir * FOURH + n] + b2[dir * FOURH + n];
    }

    // 4096 chunks per stage (A-hi 1024, A-lo 1024, W 2048); 16 per thread
    int cidx[16];
#pragma unroll
    for (int i = 0; i < 16; i++) cidx[i] = i * 256 + tid;

    auto load_stage = [&](int s, int kt) {
        uint32_t base = sb + (uint32_t)s * STGB;
#pragma unroll
        for (int i = 0; i < 16; i++) {
            int c = cidx[i];
            int cg = c & 7;
            uint32_t dst;
            const __half* g;
            if (c < 2048) {
                int ct = c >> 10, row = (c >> 3) & 127;
                dst = base + (uint32_t)ct * TILEB + (uint32_t)row * ROWB + (uint32_t)cg * 16;
                const __half* Ab = (ct == 0) ? Ah : Al;
                g = Ab + (size_t)(m0 + row) * KP + kt * 64 + cg * 8;
            } else {
                int wrow = (c >> 3) - 256;        // 0..255
                dst = base + (uint32_t)(2 * TILEB) + (uint32_t)wrow * ROWB + (uint32_t)cg * 16;
                int n = (wrow & 3) * 512 + prB + (wrow >> 2);
                g = Wh + (size_t)(dir * FOURH + n) * KP + kt * 64 + cg * 8;
            }
            cpa16(dst, g);
        }
        asm volatile("cp.async.commit_group;" ::: "memory");
    };

    float c[4][8][4];
#pragma unroll
    for (int mi = 0; mi < 4; mi++)
#pragma unroll
        for (int ni = 0; ni < 8; ni++)
#pragma unroll
            for (int j = 0; j < 4; j++) c[mi][ni][j] = 0.f;

    const uint32_t aRow  = (uint32_t)(wm + (lane & 15));
    const uint32_t aByte = (lane & 16) ? 16u : 0u;
    const uint32_t bRow  = (uint32_t)(wn + (lane & 7) + ((lane & 16) ? 8 : 0));
    const uint32_t bByte = (lane & 8) ? 16u : 0u;

    load_stage(0, 0);
    load_stage(1, 1);

    for (int kt = 0; kt < 16; kt++) {
        if (kt + 2 < 16) {
            load_stage((kt + 2) % 3, kt + 2);
            asm volatile("cp.async.wait_group 2;" ::: "memory");
        } else if (kt + 1 < 16) {
            asm volatile("cp.async.wait_group 1;" ::: "memory");
        } else {
            asm volatile("cp.async.wait_group 0;" ::: "memory");
        }
        __syncthreads();

        uint32_t st = sb + (uint32_t)(kt % 3) * STGB;
#pragma unroll
        for (int ks = 0; ks < 4; ks++) {
            uint32_t kb = (uint32_t)(ks * 32);
            uint32_t ah[4][4], al[4][4];
#pragma unroll
            for (int mi = 0; mi < 4; mi++) {
                uint32_t ra = (aRow + mi * 16) * ROWB + kb + aByte;
                ldm_x4(ah[mi][0], ah[mi][1], ah[mi][2], ah[mi][3], st + ra);
                ldm_x4(al[mi][0], al[mi][1], al[mi][2], al[mi][3], st + TILEB + ra);
            }
#pragma unroll
            for (int np = 0; np < 4; np++) {
                uint32_t bh[4];
                uint32_t rb = (bRow + np * 16) * ROWB + kb + bByte;
                ldm_x4(bh[0], bh[1], bh[2], bh[3], st + 2 * TILEB + rb);
#pragma unroll
                for (int mi = 0; mi < 4; mi++) {
                    MMA_F16(c[mi][np * 2 + 0], ah[mi], bh[0], bh[1]);
                    MMA_F16(c[mi][np * 2 + 0], al[mi], bh[0], bh[1]);
                    MMA_F16(c[mi][np * 2 + 1], ah[mi], bh[2], bh[3]);
                    MMA_F16(c[mi][np * 2 + 1], al[mi], bh[2], bh[3]);
                }
            }
        }
        __syncthreads();
    }

    float* outD = g_xproj + (size_t)dir * MM * FOURH;
#pragma unroll
    for (int mi = 0; mi < 4; mi++) {
        int row0 = m0 + wm + mi * 16 + (lane >> 2);
#pragma unroll
        for (int ni = 0; ni < 8; ni++) {
            int colL = wn + ni * 8 + (lane & 3) * 2;
            float bx = bias[colL], by = bias[colL + 1];
            *(float2*)&outD[(size_t)row0 * FOURH + prG + colL] =
                make_float2(c[mi][ni][0] + bx, c[mi][ni][1] + by);
            *(float2*)&outD[(size_t)(row0 + 8) * FOURH + prG + colL] =
                make_float2(c[mi][ni][2] + bx, c[mi][ni][3] + by);
        }
    }
}

// ---------------------------------------------------------------------------
// Persistent HMMA fp16 recurrence (R11 structure + early publish).
// grid = (64 blk, 2 dir), 256 threads (8 warps: 4m x 2n of m16n16).
// h split hi/lo fp16, W single fp16. 2 MMA products per fragment.
// ---------------------------------------------------------------------------
#define SM_A   0                        // 4 chunks x (hi 17408 + lo 17408)
#define SM_W   139264                   // hi[32][1040] = 33280
#define SM_ST  172544                   // staging: hi 1KB | lo 1KB | f32 2KB
#define SM_MB  176640                   // 5 mbarriers
#define SMEM_LSTM 176704

__global__ __launch_bounds__(256, 1) void lstm_mma(
    const int* __restrict__ mask,     // [B][T]
    float*     __restrict__ outp,     // [T][B][2H] (mode 1)
    int mode)
{
    extern __shared__ __align__(128) char sm[];
    const uint32_t sb = smem_u32(sm);
    uint16_t* sHhi = (uint16_t*)(sm + SM_ST);
    uint16_t* sHlo = (uint16_t*)(sm + SM_ST + 1024);
    float*    sF32 = (float*)(sm + SM_ST + 2048);

    const int dir = blockIdx.y;
    const int blk = blockIdx.x;
    const int tid = threadIdx.x;
    const int lane = tid & 31;
    const int w = tid >> 5;
    const int wm = (w >> 1) * 16;       // batch offset
    const int wn = (w & 1) * 16;        // pr offset

    const uint32_t mb0 = sb + SM_MB;
    if (tid == 0) {
        for (int c = 0; c < 5; c++) mbar_init(mb0 + c * 8, 1);
        asm volatile("fence.proxy.async.shared::cta;" ::: "memory");
        mbar_expect_tx(mb0 + 32, (uint32_t)WSLAB);
        bulk_g2s(sb + SM_W, g_Wr + (size_t)(dir * 64 + blk) * WSLAB, (uint32_t)WSLAB, mb0 + 32);
    }
    __syncthreads();
    mbar_wait(mb0 + 32, 0);

    const uint32_t aRow  = (uint32_t)(wm + (lane & 15));
    const uint32_t aByte = (lane & 16) ? 16u : 0u;
    const uint32_t bRow  = (uint32_t)(wn + (lane & 7) + ((lane & 16) ? 8 : 0));
    const uint32_t bByte = (lane & 8) ? 16u : 0u;

    const float* xprjD = g_xproj + (size_t)dir * MM * FOURH;
    const char* hbase = g_hA + (size_t)dir * 2 * HA_SZ;
    unsigned* mycnt = &g_cnt[dir][blk >> 4];      // counter this block increments
    unsigned* spincnt = &g_cnt[dir][w & 3];       // counter warp w (<4) spins on

    // cell identity
    const int r0    = wm + (lane >> 2);
    const int colp  = wn + (lane & 3) * 2;
    const int b_cell = r0 + ((lane & 1) << 3);
    const int hhA   = (wn >> 2) + ((lane >> 1) & 1);
    const int chunk = blk >> 4;
    const uint32_t klocByte = (uint32_t)((blk & 15) * 16);
    float cst[2] = {0.f, 0.f};

    for (int t = 0; t < TT; t++) {
        const int tt = dir ? (TT - 1 - t) : t;

        // Per-chunk acquire + copy: warp c (c<4) lane 0 handles chunk c
        if (w < 4 && lane == 0) {
            unsigned target = 16u * (unsigned)t;
            unsigned v;
            do {
                asm volatile("ld.acquire.gpu.u32 %0, [%1];" : "=r"(v) : "l"(spincnt) : "memory");
            } while (v < target);
            asm volatile("fence.proxy.async.shared::cta;" ::: "memory");
            const char* src = hbase + (size_t)(t & 1) * HA_SZ + (size_t)w * CH_SZ;
            mbar_expect_tx(mb0 + w * 8, (uint32_t)CH_SZ);
            bulk_g2s(sb + SM_A + (uint32_t)w * CH_SZ, src, (uint32_t)CH_SZ, mb0 + w * 8);
        }

        // Prefetch xproj fragment addends + mask
        float2 xg[2][2];
        {
            const float* base = xprjD + (size_t)tt * BB * FOURH + blk * 32;
#pragma unroll
            for (int ni = 0; ni < 2; ni++) {
                xg[ni][0] = *(const float2*)&base[(size_t)r0 * FOURH + colp + ni * 8];
                xg[ni][1] = *(const float2*)&base[(size_t)(r0 + 8) * FOURH + colp + ni * 8];
            }
        }
        const float mreg = (float)mask[b_cell * TT + tt];

        // MMA: C[64b x 32pr] = h[64x512] . Wslice^T (fp16, A-split 2 products)
        float cf[2][4];
#pragma unroll
        for (int ni = 0; ni < 2; ni++)
#pragma unroll
            for (int j = 0; j < 4; j++) cf[ni][j] = 0.f;

        const uint32_t par = (uint32_t)(t & 1);
#pragma unroll
        for (int c = 0; c < 4; c++) {
            mbar_wait(mb0 + c * 8, par);
            uint32_t baseA = sb + SM_A + (uint32_t)c * CH_SZ;
#pragma unroll
            for (int ks = 0; ks < 8; ks++) {
                uint32_t ah[4], al[4], bh[4];
                uint32_t ra = aRow * 272 + (uint32_t)ks * 32 + aByte;
                ldm_x4(ah[0], ah[1], ah[2], ah[3], baseA + ra);
                ldm_x4(al[0], al[1], al[2], al[3], baseA + CH_HALF + ra);
                uint32_t kb = ((uint32_t)(c * 8 + ks)) * 32 + bByte;
                ldm_x4(bh[0], bh[1], bh[2], bh[3], sb + SM_W + bRow * 1040 + kb);
#pragma unroll
                for (int ni = 0; ni < 2; ni++) {
                    int o = ni * 2;
                    MMA_F16(cf[ni], ah, bh[o], bh[o + 1]);
                    MMA_F16(cf[ni], al, bh[o], bh[o + 1]);
                }
            }
        }

        // Cells directly from fragments
#pragma unroll
        for (int ni = 0; ni < 2; ni++) {
            cf[ni][0] += xg[ni][0].x;  cf[ni][1] += xg[ni][0].y;
            cf[ni][2] += xg[ni][1].x;  cf[ni][3] += xg[ni][1].y;

            float sx = (lane & 1) ? cf[ni][0] : cf[ni][2];
            float sy = (lane & 1) ? cf[ni][1] : cf[ni][3];
            float rx = __shfl_xor_sync(0xffffffffu, sx, 1);
            float ry = __shfl_xor_sync(0xffffffffu, sy, 1);

            float gi, gf, gg, go;
            if (!(lane & 1)) { gi = cf[ni][0]; gf = cf[ni][1]; gg = rx; go = ry; }
            else             { gi = rx;        gf = ry;        gg = cf[ni][2]; go = cf[ni][3]; }

            float si = sig_(gi);
            float sf = sig_(gf);
            float so = sig_(go);
            float tg = 2.f * sig_(2.f * gg) - 1.f;
            float c2 = sf * cst[ni] + si * tg;
            float tc = 2.f * sig_(2.f * c2) - 1.f;
            float hn = so * tc * mreg;
            cst[ni] = c2 * mreg;

            int hh = hhA + ni * 2;
            __half hb = __float2half_rn(hn);
            __half lb = __float2half_rn(hn - __half2float(hb));
            sHhi[b_cell * 8 + hh] = __half_as_ushort(hb);
            sHlo[b_cell * 8 + hh] = __half_as_ushort(lb);
            if (mode) sF32[b_cell * 8 + hh] = hn;
        }
        __syncthreads();   // sync1: cells staged (also: all mbar_waits passed)

        // h-store group (tid<128): store h, named-barrier, EARLY publish.
        // Aux group (tid>=128): stores run concurrently with publish.
        char* hout = (char*)(hbase + (size_t)((t + 1) & 1) * HA_SZ + (size_t)chunk * CH_SZ);
        if (tid < 128) {
            if (tid < 64) {
                uint4 v = *(uint4*)((char*)sHhi + tid * 16);
                *(uint4*)(hout + tid * 272 + klocByte) = v;
            } else {
                int r = tid - 64;
                uint4 v = *(uint4*)((char*)sHlo + r * 16);
                *(uint4*)(hout + CH_HALF + r * 272 + klocByte) = v;
            }
            asm volatile("bar.sync 1, 128;" ::: "memory");
            if (tid == 0) {
                asm volatile("red.release.gpu.global.add.u32 [%0], %1;" :: "l"(mycnt), "r"(1u) : "memory");
            }
        } else if (mode == 0) {
            if (tid < 192) {
                int r = tid - 128;
                uint4 v = *(uint4*)((char*)sHhi + r * 16);
                *(uint4*)((char*)g_Ahi + ((size_t)(tt * 64 + r) * 1024 + dir * 512 + blk * 8) * 2) = v;
            } else {
                int r = tid - 192;
                uint4 v = *(uint4*)((char*)sHlo + r * 16);
                *(uint4*)((char*)g_Alo + ((size_t)(tt * 64 + r) * 1024 + dir * 512 + blk * 8) * 2) = v;
            }
        } else {
            int r = (tid - 128) >> 1, half = tid & 1;
            float4 v = *(float4*)((char*)sF32 + r * 32 + half * 16);
            *(float4*)&outp[((size_t)tt * 64 + r) * 1024 + dir * 512 + blk * 8 + half * 4] = v;
        }

        __syncthreads();   // sync2: guards sHhi/sF32 reuse + mbar re-arm
    }
}

// ---------------------------------------------------------------------------
// kernel_launch
// ---------------------------------------------------------------------------
extern "C" void kernel_launch(void* const* d_in, const int* in_sizes, int n_in,
                              void* d_out, int out_size)
{
    const float* x    = (const float*)d_in[0];
    const int*   mask = (const int*)  d_in[1];
    const float* w_ih = (const float*)d_in[2];
    const float* w_hh = (const float*)d_in[3];
    const float* b_ih = (const float*)d_in[4];
    const float* b_hh = (const float*)d_in[5];
    float* out = (float*)d_out;

    __half *pAh, *pAl, *pWh;
    cudaGetSymbolAddress((void**)&pAh, g_Ahi);
    cudaGetSymbolAddress((void**)&pAl, g_Alo);
    cudaGetSymbolAddress((void**)&pWh, g_Whi);

    cudaFuncSetAttribute(lstm_mma,
                         cudaFuncAttributeMaxDynamicSharedMemorySize, SMEM_LSTM);
    cudaFuncSetAttribute(proj_mma,
                         cudaFuncAttributeMaxDynamicSharedMemorySize, SMEM_PROJ);

    dim3 gproj(128, 16);
    dim3 gpers(64, 2);

    for (int layer = 0; layer < 2; layer++) {
        if (layer == 0) pack_f16_split<<<8192, 256>>>(x, pAh, pAl);
        // layer 1: g_Ahi/g_Alo already written by layer-0 lstm_mma

        pack_f16_single<<<2048, 256>>>(w_ih + (size_t)layer * 2 * FOURH * KP, pWh);
        pack_Wr<<<128, 256>>>(w_hh + (size_t)layer * 2 * FOURH * HH);

        proj_mma<<<gproj, 256, SMEM_PROJ>>>(
            pAh, pAl, pWh,
            b_ih + (size_t)layer * 2 * FOURH,
            b_hh + (size_t)layer * 2 * FOURH);

        lstm_mma<<<gpers, 256, SMEM_LSTM>>>(mask, (layer == 1) ? out : nullptr, layer);
    }
}

// round 13
// speedup vs baseline: 1.3443x; 1.0148x over previous
#include <cuda_runtime.h>
#include <cuda_fp16.h>
#include <math.h>
#include <stdint.h>

// Problem constants
#define TT     256
#define BB     64
#define HH     512
#define FOURH  2048
#define KP     1024
#define MM     (TT*BB)     // 16384

// ---------------------------------------------------------------------------
// Device scratch (static only)
// ---------------------------------------------------------------------------
__device__ float g_xproj[(size_t)2*MM*FOURH];        // input projections, pr-packed cols
__device__ unsigned g_cnt[2][4];                     // per (dir, chunk) producer counters

// proj operands: fp16. A split hi/lo; W hi only. Layer-1 A written by lstm_mma.
__device__ __align__(16) __half g_Ahi[(size_t)MM*KP];
__device__ __align__(16) __half g_Alo[(size_t)MM*KP];
__device__ __align__(16) __half g_Whi[(size_t)4096*KP];

// recurrence W_hh: per (dir, block) slab: hi[32][1040B] (fp16, no lo)
#define WSLAB 33280
__device__ __align__(128) char g_Wr[(size_t)2*64*WSLAB];

// recurrence h state: [dir][ping][chunk4]{ hi[64][272B], lo[64][272B] } (fp16)
#define CH_HALF 17408
#define CH_SZ   34816
#define HA_SZ   (4*CH_SZ)    // 139264 per (dir,ping)
__device__ __align__(128) char g_hA[(size_t)2*2*HA_SZ];

// ---------------------------------------------------------------------------
// PTX helpers
// ---------------------------------------------------------------------------
__device__ __forceinline__ uint32_t smem_u32(const void* p) {
    uint32_t a;
    asm("{ .reg .u64 t; cvta.to.shared.u64 t, %1; cvt.u32.u64 %0, t; }" : "=r"(a) : "l"(p));
    return a;
}
__device__ __forceinline__ void mbar_init(uint32_t mb, uint32_t cnt) {
    asm volatile("mbarrier.init.shared.b64 [%0], %1;" :: "r"(mb), "r"(cnt) : "memory");
}
__device__ __forceinline__ void mbar_expect_tx(uint32_t mb, uint32_t bytes) {
    asm volatile("mbarrier.arrive.expect_tx.shared.b64 _, [%0], %1;" :: "r"(mb), "r"(bytes) : "memory");
}
__device__ __forceinline__ void bulk_g2s(uint32_t dst, const void* src, uint32_t bytes, uint32_t mb) {
    asm volatile("cp.async.bulk.shared::cta.global.mbarrier::complete_tx::bytes [%0], [%1], %2, [%3];"
                 :: "r"(dst), "l"(src), "r"(bytes), "r"(mb) : "memory");
}
__device__ __forceinline__ void mbar_wait(uint32_t mb, uint32_t parity) {
    uint32_t done;
    asm volatile("{\n\t.reg .pred p;\n\t"
        "mbarrier.try_wait.parity.acquire.cta.shared::cta.b64 p, [%1], %2;\n\t"
        "selp.b32 %0, 1, 0, p;\n\t}"
        : "=r"(done) : "r"(mb), "r"(parity) : "memory");
    while (!done) {
        asm volatile("{\n\t.reg .pred p;\n\t"
            "mbarrier.try_wait.parity.acquire.cta.shared::cta.b64 p, [%1], %2, 0x989680;\n\t"
            "selp.b32 %0, 1, 0, p;\n\t}"
            : "=r"(done) : "r"(mb), "r"(parity) : "memory");
    }
}
__device__ __forceinline__ void cpa16(uint32_t dst, const void* src) {
    asm volatile("cp.async.cg.shared.global [%0], [%1], 16;" :: "r"(dst), "l"(src) : "memory");
}
__device__ __forceinline__ void ldm_x4(uint32_t& r0, uint32_t& r1, uint32_t& r2, uint32_t& r3,
                                       uint32_t addr) {
    asm volatile("ldmatrix.sync.aligned.m8n8.x4.shared.b16 {%0,%1,%2,%3}, [%4];"
                 : "=r"(r0), "=r"(r1), "=r"(r2), "=r"(r3) : "r"(addr));
}
#define MMA_F16(c, a, b0v, b1v) \
    asm volatile("mma.sync.aligned.m16n8k16.row.col.f32.f16.f16.f32 " \
        "{%0,%1,%2,%3}, {%4,%5,%6,%7}, {%8,%9}, {%0,%1,%2,%3};" \
        : "+f"((c)[0]), "+f"((c)[1]), "+f"((c)[2]), "+f"((c)[3]) \
        : "r"((a)[0]), "r"((a)[1]), "r"((a)[2]), "r"((a)[3]), "r"(b0v), "r"(b1v))

__device__ __forceinline__ float sig_(float x) {
    return __fdividef(1.f, 1.f + __expf(-x));
}
__device__ __forceinline__ uint32_t pack_hilo16(float a, float b, uint32_t& lo) {
    __half h0 = __float2half_rn(a);
    __half h1 = __float2half_rn(b);
    __half l0 = __float2half_rn(a - __half2float(h0));
    __half l1 = __float2half_rn(b - __half2float(h1));
    lo = (uint32_t)__half_as_ushort(l0) | ((uint32_t)__half_as_ushort(l1) << 16);
    return (uint32_t)__half_as_ushort(h0) | ((uint32_t)__half_as_ushort(h1) << 16);
}

// ---------------------------------------------------------------------------
// Pack fp32 -> hi/lo fp16 (A operand), 8 elems/thread
// ---------------------------------------------------------------------------
__global__ __launch_bounds__(256) void pack_f16_split(
    const float* __restrict__ src,
    __half* __restrict__ hi, __half* __restrict__ lo)
{
    size_t i = ((size_t)blockIdx.x * 256 + threadIdx.x) * 8;
    float4 v0 = *(const float4*)(src + i);
    float4 v1 = *(const float4*)(src + i + 4);
    float xv[8] = {v0.x, v0.y, v0.z, v0.w, v1.x, v1.y, v1.z, v1.w};
    uint32_t hp[4], lp[4];
#pragma unroll
    for (int e = 0; e < 4; e++) hp[e] = pack_hilo16(xv[2*e], xv[2*e+1], lp[e]);
    *(uint4*)(hi + i) = make_uint4(hp[0], hp[1], hp[2], hp[3]);
    *(uint4*)(lo + i) = make_uint4(lp[0], lp[1], lp[2], lp[3]);
}

// ---------------------------------------------------------------------------
// Pack fp32 -> single fp16 (W operand), 8 elems/thread
// ---------------------------------------------------------------------------
__global__ __launch_bounds__(256) void pack_f16_single(
    const float* __restrict__ src, __half* __restrict__ hi)
{
    size_t i = ((size_t)blockIdx.x * 256 + threadIdx.x) * 8;
    float4 v0 = *(const float4*)(src + i);
    float4 v1 = *(const float4*)(src + i + 4);
    float xv[8] = {v0.x, v0.y, v0.z, v0.w, v1.x, v1.y, v1.z, v1.w};
    uint32_t hp[4];
#pragma unroll
    for (int e = 0; e < 4; e++) {
        __half h0 = __float2half_rn(xv[2*e]);
        __half h1 = __float2half_rn(xv[2*e+1]);
        hp[e] = (uint32_t)__half_as_ushort(h0) | ((uint32_t)__half_as_ushort(h1) << 16);
    }
    *(uint4*)(hi + i) = make_uint4(hp[0], hp[1], hp[2], hp[3]);
}

// ---------------------------------------------------------------------------
// Pack W_hh into per-block slabs (fp16 hi only): row pr=hh*4+g.
// Also zeros h slot 0 (both dirs) + producer counters (fused zero_state).
// grid = 128
// ---------------------------------------------------------------------------
__global__ __launch_bounds__(256) void pack_Wr(const float* __restrict__ whh) {
    const int dir = blockIdx.x >> 6, blk = blockIdx.x & 63;
    char* slab = g_Wr + (size_t)(dir * 64 + blk) * WSLAB;
    for (int i = threadIdx.x; i < 8192; i += 256) {
        int r = i >> 8;
        int k2 = (i & 255) * 2;
        int hh = r >> 2, g = r & 3;
        int grow = g * HH + blk * 8 + hh;
        float2 v = *(const float2*)&whh[((size_t)dir * FOURH + grow) * HH + k2];
        __half h0 = __float2half_rn(v.x);
        __half h1 = __float2half_rn(v.y);
        *(uint32_t*)(slab + r * 1040 + k2 * 2) =
            (uint32_t)__half_as_ushort(h0) | ((uint32_t)__half_as_ushort(h1) << 16);
    }
    uint32_t gid = blockIdx.x * 256 + threadIdx.x;
    float* p = (float*)g_hA;
    for (uint32_t i = gid; i < HA_SZ / 4; i += 32768) {
        p[i] = 0.f;                       // dir0 ping0
        p[i + (2 * HA_SZ) / 4] = 0.f;     // dir1 ping0
    }
    if (gid < 8) ((unsigned*)g_cnt)[gid] = 0u;
}

// ---------------------------------------------------------------------------
// HMMA fp16 projection GEMM, 3-stage pipeline, ONE sync per kt.
// CTA tile 128m x 256pr x 64k; 8 warps = 2m x 4n, warp tile 64m x 64pr.
// Loop: wait_group; sync; refill stage (kt+2)%3; compute stage kt%3.
// (Safe: stage (kt+2)%3 was consumed in iter kt-1; all readers passed this
//  iteration's sync before the refill cp.asyncs are issued.)
// ---------------------------------------------------------------------------
#define ROWB   144
#define TILEB  (128*ROWB)                 // 18432
#define WTILEB (256*ROWB)                 // 36864
#define STGB   (2*TILEB + WTILEB)         // 73728
#define OFF_BIAS (3*STGB)                 // 221184
#define SMEM_PROJ (OFF_BIAS + 1088)

__global__ __launch_bounds__(256, 1) void proj_mma(
    const __half* __restrict__ Ah, const __half* __restrict__ Al,
    const __half* __restrict__ Wh,
    const float* __restrict__ b1, const float* __restrict__ b2)
{
    extern __shared__ __align__(128) char smp[];
    const uint32_t sb = smem_u32(smp);
    float* bias = (float*)(smp + OFF_BIAS);

    const int tid  = threadIdx.x;
    const int lane = tid & 31;
    const int w    = tid >> 5;
    const int m0   = blockIdx.x * 128;
    const int dir  = blockIdx.y >> 3;
    const int prG  = (blockIdx.y & 7) * 256;
    const int prB  = prG >> 2;
    const int wm   = (w >> 2) * 64;
    const int wn   = (w & 3) * 64;

    {
        int n = (tid & 3) * 512 + prB + (tid >> 2);
        bias[tid] = b1[dir * FOURH + n] + b2[dir * FOURH + n];
    }

    int cidx[16];
#pragma unroll
    for (int i = 0; i < 16; i++) cidx[i] = i * 256 + tid;

    auto load_stage = [&](int s, int kt) {
        uint32_t base = sb + (uint32_t)s * STGB;
#pragma unroll
        for (int i = 0; i < 16; i++) {
            int c = cidx[i];
            int cg = c & 7;
            uint32_t dst;
            const __half* g;
            if (c < 2048) {
                int ct = c >> 10, row = (c >> 3) & 127;
                dst = base + (uint32_t)ct * TILEB + (uint32_t)row * ROWB + (uint32_t)cg * 16;
                const __half* Ab = (ct == 0) ? Ah : Al;
                g = Ab + (size_t)(m0 + row) * KP + kt * 64 + cg * 8;
            } else {
                int wrow = (c >> 3) - 256;
                dst = base + (uint32_t)(2 * TILEB) + (uint32_t)wrow * ROWB + (uint32_t)cg * 16;
                int n = (wrow & 3) * 512 + prB + (wrow >> 2);
                g = Wh + (size_t)(dir * FOURH + n) * KP + kt * 64 + cg * 8;
            }
            cpa16(dst, g);
        }
        asm volatile("cp.async.commit_group;" ::: "memory");
    };

    float c[4][8][4];
#pragma unroll
    for (int mi = 0; mi < 4; mi++)
#pragma unroll
        for (int ni = 0; ni < 8; ni++)
#pragma unroll
            for (int j = 0; j < 4; j++) c[mi][ni][j] = 0.f;

    const uint32_t aRow  = (uint32_t)(wm + (lane & 15));
    const uint32_t aByte = (lane & 16) ? 16u : 0u;
    const uint32_t bRow  = (uint32_t)(wn + (lane & 7) + ((lane & 16) ? 8 : 0));
    const uint32_t bByte = (lane & 8) ? 16u : 0u;

    load_stage(0, 0);
    load_stage(1, 1);

    for (int kt = 0; kt < 16; kt++) {
        // Thread-own copies for stage kt complete (leave ≤1 newer group pending)
        if (kt < 15) {
            asm volatile("cp.async.wait_group 1;" ::: "memory");
        } else {
            asm volatile("cp.async.wait_group 0;" ::: "memory");
        }
        __syncthreads();   // single sync: visibility of stage kt + all readers of stage (kt+2)%3 done

        if (kt + 2 < 16) load_stage((kt + 2) % 3, kt + 2);

        uint32_t st = sb + (uint32_t)(kt % 3) * STGB;
#pragma unroll
        for (int ks = 0; ks < 4; ks++) {
            uint32_t kb = (uint32_t)(ks * 32);
            uint32_t ah[4][4], al[4][4];
#pragma unroll
            for (int mi = 0; mi < 4; mi++) {
                uint32_t ra = (aRow + mi * 16) * ROWB + kb + aByte;
                ldm_x4(ah[mi][0], ah[mi][1], ah[mi][2], ah[mi][3], st + ra);
                ldm_x4(al[mi][0], al[mi][1], al[mi][2], al[mi][3], st + TILEB + ra);
            }
#pragma unroll
            for (int np = 0; np < 4; np++) {
                uint32_t bh[4];
                uint32_t rb = (bRow + np * 16) * ROWB + kb + bByte;
                ldm_x4(bh[0], bh[1], bh[2], bh[3], st + 2 * TILEB + rb);
#pragma unroll
                for (int mi = 0; mi < 4; mi++) {
                    MMA_F16(c[mi][np * 2 + 0], ah[mi], bh[0], bh[1]);
                    MMA_F16(c[mi][np * 2 + 0], al[mi], bh[0], bh[1]);
                    MMA_F16(c[mi][np * 2 + 1], ah[mi], bh[2], bh[3]);
                    MMA_F16(c[mi][np * 2 + 1], al[mi], bh[2], bh[3]);
                }
            }
        }
    }

    float* outD = g_xproj + (size_t)dir * MM * FOURH;
#pragma unroll
    for (int mi = 0; mi < 4; mi++) {
        int row0 = m0 + wm + mi * 16 + (lane >> 2);
#pragma unroll
        for (int ni = 0; ni < 8; ni++) {
            int colL = wn + ni * 8 + (lane & 3) * 2;
            float bx = bias[colL], by = bias[colL + 1];
            *(float2*)&outD[(size_t)row0 * FOURH + prG + colL] =
                make_float2(c[mi][ni][0] + bx, c[mi][ni][1] + by);
            *(float2*)&outD[(size_t)(row0 + 8) * FOURH + prG + colL] =
                make_float2(c[mi][ni][2] + bx, c[mi][ni][3] + by);
        }
    }
}

// ---------------------------------------------------------------------------
// Persistent HMMA fp16 recurrence (unchanged from R12 — proven).
// grid = (64 blk, 2 dir), 256 threads (8 warps: 4m x 2n of m16n16).
// ---------------------------------------------------------------------------
#define SM_A   0                        // 4 chunks x (hi 17408 + lo 17408)
#define SM_W   139264                   // hi[32][1040] = 33280
#define SM_ST  172544                   // staging: hi 1KB | lo 1KB | f32 2KB
#define SM_MB  176640                   // 5 mbarriers
#define SMEM_LSTM 176704

__global__ __launch_bounds__(256, 1) void lstm_mma(
    const int* __restrict__ mask,     // [B][T]
    float*     __restrict__ outp,     // [T][B][2H] (mode 1)
    int mode)
{
    extern __shared__ __align__(128) char sm[];
    const uint32_t sb = smem_u32(sm);
    uint16_t* sHhi = (uint16_t*)(sm + SM_ST);
    uint16_t* sHlo = (uint16_t*)(sm + SM_ST + 1024);
    float*    sF32 = (float*)(sm + SM_ST + 2048);

    const int dir = blockIdx.y;
    const int blk = blockIdx.x;
    const int tid = threadIdx.x;
    const int lane = tid & 31;
    const int w = tid >> 5;
    const int wm = (w >> 1) * 16;       // batch offset
    const int wn = (w & 1) * 16;        // pr offset

    const uint32_t mb0 = sb + SM_MB;
    if (tid == 0) {
        for (int c = 0; c < 5; c++) mbar_init(mb0 + c * 8, 1);
        asm volatile("fence.proxy.async.shared::cta;" ::: "memory");
        mbar_expect_tx(mb0 + 32, (uint32_t)WSLAB);
        bulk_g2s(sb + SM_W, g_Wr + (size_t)(dir * 64 + blk) * WSLAB, (uint32_t)WSLAB, mb0 + 32);
    }
    __syncthreads();
    mbar_wait(mb0 + 32, 0);

    const uint32_t aRow  = (uint32_t)(wm + (lane & 15));
    const uint32_t aByte = (lane & 16) ? 16u : 0u;
    const uint32_t bRow  = (uint32_t)(wn + (lane & 7) + ((lane & 16) ? 8 : 0));
    const uint32_t bByte = (lane & 8) ? 16u : 0u;

    const float* xprjD = g_xproj + (size_t)dir * MM * FOURH;
    const char* hbase = g_hA + (size_t)dir * 2 * HA_SZ;
    unsigned* mycnt = &g_cnt[dir][blk >> 4];
    unsigned* spincnt = &g_cnt[dir][w & 3];

    const int r0    = wm + (lane >> 2);
    const int colp  = wn + (lane & 3) * 2;
    const int b_cell = r0 + ((lane & 1) << 3);
    const int hhA   = (wn >> 2) + ((lane >> 1) & 1);
    const int chunk = blk >> 4;
    const uint32_t klocByte = (uint32_t)((blk & 15) * 16);
    float cst[2] = {0.f, 0.f};

    for (int t = 0; t < TT; t++) {
        const int tt = dir ? (TT - 1 - t) : t;

        if (w < 4 && lane == 0) {
            unsigned target = 16u * (unsigned)t;
            unsigned v;
            do {
                asm volatile("ld.acquire.gpu.u32 %0, [%1];" : "=r"(v) : "l"(spincnt) : "memory");
            } while (v < target);
            asm volatile("fence.proxy.async.shared::cta;" ::: "memory");
            const char* src = hbase + (size_t)(t & 1) * HA_SZ + (size_t)w * CH_SZ;
            mbar_expect_tx(mb0 + w * 8, (uint32_t)CH_SZ);
            bulk_g2s(sb + SM_A + (uint32_t)w * CH_SZ, src, (uint32_t)CH_SZ, mb0 + w * 8);
        }

        float2 xg[2][2];
        {
            const float* base = xprjD + (size_t)tt * BB * FOURH + blk * 32;
#pragma unroll
            for (int ni = 0; ni < 2; ni++) {
                xg[ni][0] = *(const float2*)&base[(size_t)r0 * FOURH + colp + ni * 8];
                xg[ni][1] = *(const float2*)&base[(size_t)(r0 + 8) * FOURH + colp + ni * 8];
            }
        }
        const float mreg = (float)mask[b_cell * TT + tt];

        float cf[2][4];
#pragma unroll
        for (int ni = 0; ni < 2; ni++)
#pragma unroll
            for (int j = 0; j < 4; j++) cf[ni][j] = 0.f;

        const uint32_t par = (uint32_t)(t & 1);
#pragma unroll
        for (int c = 0; c < 4; c++) {
            mbar_wait(mb0 + c * 8, par);
            uint32_t baseA = sb + SM_A + (uint32_t)c * CH_SZ;
#pragma unroll
            for (int ks = 0; ks < 8; ks++) {
                uint32_t ah[4], al[4], bh[4];
                uint32_t ra = aRow * 272 + (uint32_t)ks * 32 + aByte;
                ldm_x4(ah[0], ah[1], ah[2], ah[3], baseA + ra);
                ldm_x4(al[0], al[1], al[2], al[3], baseA + CH_HALF + ra);
                uint32_t kb = ((uint32_t)(c * 8 + ks)) * 32 + bByte;
                ldm_x4(bh[0], bh[1], bh[2], bh[3], sb + SM_W + bRow * 1040 + kb);
#pragma unroll
                for (int ni = 0; ni < 2; ni++) {
                    int o = ni * 2;
                    MMA_F16(cf[ni], ah, bh[o], bh[o + 1]);
                    MMA_F16(cf[ni], al, bh[o], bh[o + 1]);
                }
            }
        }

#pragma unroll
        for (int ni = 0; ni < 2; ni++) {
            cf[ni][0] += xg[ni][0].x;  cf[ni][1] += xg[ni][0].y;
            cf[ni][2] += xg[ni][1].x;  cf[ni][3] += xg[ni][1].y;

            float sx = (lane & 1) ? cf[ni][0] : cf[ni][2];
            float sy = (lane & 1) ? cf[ni][1] : cf[ni][3];
            float rx = __shfl_xor_sync(0xffffffffu, sx, 1);
            float ry = __shfl_xor_sync(0xffffffffu, sy, 1);

            float gi, gf, gg, go;
            if (!(lane & 1)) { gi = cf[ni][0]; gf = cf[ni][1]; gg = rx; go = ry; }
            else             { gi = rx;        gf = ry;        gg = cf[ni][2]; go = cf[ni][3]; }

            float si = sig_(gi);
            float sf = sig_(gf);
            float so = sig_(go);
            float tg = 2.f * sig_(2.f * gg) - 1.f;
            float c2 = sf * cst[ni] + si * tg;
            float tc = 2.f * sig_(2.f * c2) - 1.f;
            float hn = so * tc * mreg;
            cst[ni] = c2 * mreg;

            int hh = hhA + ni * 2;
            __half hb = __float2half_rn(hn);
            __half lb = __float2half_rn(hn - __half2float(hb));
            sHhi[b_cell * 8 + hh] = __half_as_ushort(hb);
            sHlo[b_cell * 8 + hh] = __half_as_ushort(lb);
            if (mode) sF32[b_cell * 8 + hh] = hn;
        }
        __syncthreads();   // sync1: cells staged (also: all mbar_waits passed)

        char* hout = (char*)(hbase + (size_t)((t + 1) & 1) * HA_SZ + (size_t)chunk * CH_SZ);
        if (tid < 128) {
            if (tid < 64) {
                uint4 v = *(uint4*)((char*)sHhi + tid * 16);
                *(uint4*)(hout + tid * 272 + klocByte) = v;
            } else {
                int r = tid - 64;
                uint4 v = *(uint4*)((char*)sHlo + r * 16);
                *(uint4*)(hout + CH_HALF + r * 272 + klocByte) = v;
            }
            asm volatile("bar.sync 1, 128;" ::: "memory");
            if (tid == 0) {
                asm volatile("red.release.gpu.global.add.u32 [%0], %1;" :: "l"(mycnt), "r"(1u) : "memory");
            }
        } else if (mode == 0) {
            if (tid < 192) {
                int r = tid - 128;
                uint4 v = *(uint4*)((char*)sHhi + r * 16);
                *(uint4*)((char*)g_Ahi + ((size_t)(tt * 64 + r) * 1024 + dir * 512 + blk * 8) * 2) = v;
            } else {
                int r = tid - 192;
                uint4 v = *(uint4*)((char*)sHlo + r * 16);
                *(uint4*)((char*)g_Alo + ((size_t)(tt * 64 + r) * 1024 + dir * 512 + blk * 8) * 2) = v;
            }
        } else {
            int r = (tid - 128) >> 1, half = tid & 1;
            float4 v = *(float4*)((char*)sF32 + r * 32 + half * 16);
            *(float4*)&outp[((size_t)tt * 64 + r) * 1024 + dir * 512 + blk * 8 + half * 4] = v;
        }

        __syncthreads();   // sync2: guards sHhi/sF32 reuse + mbar re-arm
    }
}

// ---------------------------------------------------------------------------
// kernel_launch
// ---------------------------------------------------------------------------
extern "C" void kernel_launch(void* const* d_in, const int* in_sizes, int n_in,
                              void* d_out, int out_size)
{
    const float* x    = (const float*)d_in[0];
    const int*   mask = (const int*)  d_in[1];
    const float* w_ih = (const float*)d_in[2];
    const float* w_hh = (const float*)d_in[3];
    const float* b_ih = (const float*)d_in[4];
    const float* b_hh = (const float*)d_in[5];
    float* out = (float*)d_out;

    __half *pAh, *pAl, *pWh;
    cudaGetSymbolAddress((void**)&pAh, g_Ahi);
    cudaGetSymbolAddress((void**)&pAl, g_Alo);
    cudaGetSymbolAddress((void**)&pWh, g_Whi);

    cudaFuncSetAttribute(lstm_mma,
                         cudaFuncAttributeMaxDynamicSharedMemorySize, SMEM_LSTM);
    cudaFuncSetAttribute(proj_mma,
                         cudaFuncAttributeMaxDynamicSharedMemorySize, SMEM_PROJ);

    dim3 gproj(128, 16);
    dim3 gpers(64, 2);

    for (int layer = 0; layer < 2; layer++) {
        if (layer == 0) pack_f16_split<<<8192, 256>>>(x, pAh, pAl);
        // layer 1: g_Ahi/g_Alo already written by layer-0 lstm_mma

        pack_f16_single<<<2048, 256>>>(w_ih + (size_t)layer * 2 * FOURH * KP, pWh);
        pack_Wr<<<128, 256>>>(w_hh + (size_t)layer * 2 * FOURH * HH);

        proj_mma<<<gproj, 256, SMEM_PROJ>>>(
            pAh, pAl, pWh,
            b_ih + (size_t)layer * 2 * FOURH,
            b_hh + (size_t)layer * 2 * FOURH);

        lstm_mma<<<gpers, 256, SMEM_LSTM>>>(mask, (layer == 1) ? out : nullptr, layer);
    }
}

// round 14
// speedup vs baseline: 1.3632x; 1.0141x over previous
#include <cuda_runtime.h>
#include <cuda_fp16.h>
#include <math.h>
#include <stdint.h>

// Problem constants
#define TT     256
#define BB     64
#define HH     512
#define FOURH  2048
#define KP     1024
#define MM     (TT*BB)     // 16384

// ---------------------------------------------------------------------------
// Device scratch (static only)
// ---------------------------------------------------------------------------
__device__ float g_xproj[(size_t)2*MM*FOURH];        // input projections, pr-packed cols
__device__ unsigned g_cnt[2][4];                     // per (dir, chunk) producer counters

// proj operands: fp16. A split hi/lo; W hi only. Layer-1 A written by lstm_mma.
__device__ __align__(16) __half g_Ahi[(size_t)MM*KP];
__device__ __align__(16) __half g_Alo[(size_t)MM*KP];
__device__ __align__(16) __half g_Whi[(size_t)4096*KP];

// recurrence W_hh: per (dir, block) slab: hi[32][1040B] (fp16, no lo)
#define WSLAB 33280
__device__ __align__(128) char g_Wr[(size_t)2*64*WSLAB];

// recurrence h state: [dir][ping][chunk4]{ hi[64][272B], lo[64][272B] } (fp16)
#define CH_HALF 17408
#define CH_SZ   34816
#define HA_SZ   (4*CH_SZ)    // 139264 per (dir,ping)
__device__ __align__(128) char g_hA[(size_t)2*2*HA_SZ];

// ---------------------------------------------------------------------------
// PTX helpers
// ---------------------------------------------------------------------------
__device__ __forceinline__ uint32_t smem_u32(const void* p) {
    uint32_t a;
    asm("{ .reg .u64 t; cvta.to.shared.u64 t, %1; cvt.u32.u64 %0, t; }" : "=r"(a) : "l"(p));
    return a;
}
__device__ __forceinline__ void mbar_init(uint32_t mb, uint32_t cnt) {
    asm volatile("mbarrier.init.shared.b64 [%0], %1;" :: "r"(mb), "r"(cnt) : "memory");
}
__device__ __forceinline__ void mbar_expect_tx(uint32_t mb, uint32_t bytes) {
    asm volatile("mbarrier.arrive.expect_tx.shared.b64 _, [%0], %1;" :: "r"(mb), "r"(bytes) : "memory");
}
__device__ __forceinline__ void bulk_g2s(uint32_t dst, const void* src, uint32_t bytes, uint32_t mb) {
    asm volatile("cp.async.bulk.shared::cta.global.mbarrier::complete_tx::bytes [%0], [%1], %2, [%3];"
                 :: "r"(dst), "l"(src), "r"(bytes), "r"(mb) : "memory");
}
__device__ __forceinline__ void mbar_wait(uint32_t mb, uint32_t parity) {
    uint32_t done;
    asm volatile("{\n\t.reg .pred p;\n\t"
        "mbarrier.try_wait.parity.acquire.cta.shared::cta.b64 p, [%1], %2;\n\t"
        "selp.b32 %0, 1, 0, p;\n\t}"
        : "=r"(done) : "r"(mb), "r"(parity) : "memory");
    while (!done) {
        asm volatile("{\n\t.reg .pred p;\n\t"
            "mbarrier.try_wait.parity.acquire.cta.shared::cta.b64 p, [%1], %2, 0x989680;\n\t"
            "selp.b32 %0, 1, 0, p;\n\t}"
            : "=r"(done) : "r"(mb), "r"(parity) : "memory");
    }
}
__device__ __forceinline__ void cpa16(uint32_t dst, const void* src) {
    asm volatile("cp.async.cg.shared.global [%0], [%1], 16;" :: "r"(dst), "l"(src) : "memory");
}
__device__ __forceinline__ void ldm_x4(uint32_t& r0, uint32_t& r1, uint32_t& r2, uint32_t& r3,
                                       uint32_t addr) {
    asm volatile("ldmatrix.sync.aligned.m8n8.x4.shared.b16 {%0,%1,%2,%3}, [%4];"
                 : "=r"(r0), "=r"(r1), "=r"(r2), "=r"(r3) : "r"(addr));
}
#define MMA_F16(c, a, b0v, b1v) \
    asm volatile("mma.sync.aligned.m16n8k16.row.col.f32.f16.f16.f32 " \
        "{%0,%1,%2,%3}, {%4,%5,%6,%7}, {%8,%9}, {%0,%1,%2,%3};" \
        : "+f"((c)[0]), "+f"((c)[1]), "+f"((c)[2]), "+f"((c)[3]) \
        : "r"((a)[0]), "r"((a)[1]), "r"((a)[2]), "r"((a)[3]), "r"(b0v), "r"(b1v))

__device__ __forceinline__ float sig_(float x) {
    return __fdividef(1.f, 1.f + __expf(-x));
}
__device__ __forceinline__ uint32_t pack_hilo16(float a, float b, uint32_t& lo) {
    __half h0 = __float2half_rn(a);
    __half h1 = __float2half_rn(b);
    __half l0 = __float2half_rn(a - __half2float(h0));
    __half l1 = __float2half_rn(b - __half2float(h1));
    lo = (uint32_t)__half_as_ushort(l0) | ((uint32_t)__half_as_ushort(l1) << 16);
    return (uint32_t)__half_as_ushort(h0) | ((uint32_t)__half_as_ushort(h1) << 16);
}

// ---------------------------------------------------------------------------
// Pack fp32 -> hi/lo fp16 (A operand), 8 elems/thread
// ---------------------------------------------------------------------------
__global__ __launch_bounds__(256) void pack_f16_split(
    const float* __restrict__ src,
    __half* __restrict__ hi, __half* __restrict__ lo)
{
    size_t i = ((size_t)blockIdx.x * 256 + threadIdx.x) * 8;
    float4 v0 = *(const float4*)(src + i);
    float4 v1 = *(const float4*)(src + i + 4);
    float xv[8] = {v0.x, v0.y, v0.z, v0.w, v1.x, v1.y, v1.z, v1.w};
    uint32_t hp[4], lp[4];
#pragma unroll
    for (int e = 0; e < 4; e++) hp[e] = pack_hilo16(xv[2*e], xv[2*e+1], lp[e]);
    *(uint4*)(hi + i) = make_uint4(hp[0], hp[1], hp[2], hp[3]);
    *(uint4*)(lo + i) = make_uint4(lp[0], lp[1], lp[2], lp[3]);
}

// ---------------------------------------------------------------------------
// Pack fp32 -> single fp16 (W operand), 8 elems/thread
// ---------------------------------------------------------------------------
__global__ __launch_bounds__(256) void pack_f16_single(
    const float* __restrict__ src, __half* __restrict__ hi)
{
    size_t i = ((size_t)blockIdx.x * 256 + threadIdx.x) * 8;
    float4 v0 = *(const float4*)(src + i);
    float4 v1 = *(const float4*)(src + i + 4);
    float xv[8] = {v0.x, v0.y, v0.z, v0.w, v1.x, v1.y, v1.z, v1.w};
    uint32_t hp[4];
#pragma unroll
    for (int e = 0; e < 4; e++) {
        __half h0 = __float2half_rn(xv[2*e]);
        __half h1 = __float2half_rn(xv[2*e+1]);
        hp[e] = (uint32_t)__half_as_ushort(h0) | ((uint32_t)__half_as_ushort(h1) << 16);
    }
    *(uint4*)(hi + i) = make_uint4(hp[0], hp[1], hp[2], hp[3]);
}

// ---------------------------------------------------------------------------
// Pack W_hh into per-block slabs (fp16 hi only): row pr=hh*4+g.
// Also zeros h slot 0 (both dirs) + producer counters (fused zero_state).
// grid = 128
// ---------------------------------------------------------------------------
__global__ __launch_bounds__(256) void pack_Wr(const float* __restrict__ whh) {
    const int dir = blockIdx.x >> 6, blk = blockIdx.x & 63;
    char* slab = g_Wr + (size_t)(dir * 64 + blk) * WSLAB;
    for (int i = threadIdx.x; i < 8192; i += 256) {
        int r = i >> 8;
        int k2 = (i & 255) * 2;
        int hh = r >> 2, g = r & 3;
        int grow = g * HH + blk * 8 + hh;
        float2 v = *(const float2*)&whh[((size_t)dir * FOURH + grow) * HH + k2];
        __half h0 = __float2half_rn(v.x);
        __half h1 = __float2half_rn(v.y);
        *(uint32_t*)(slab + r * 1040 + k2 * 2) =
            (uint32_t)__half_as_ushort(h0) | ((uint32_t)__half_as_ushort(h1) << 16);
    }
    uint32_t gid = blockIdx.x * 256 + threadIdx.x;
    float* p = (float*)g_hA;
    for (uint32_t i = gid; i < HA_SZ / 4; i += 32768) {
        p[i] = 0.f;                       // dir0 ping0
        p[i + (2 * HA_SZ) / 4] = 0.f;     // dir1 ping0
    }
    if (gid < 8) ((unsigned*)g_cnt)[gid] = 0u;
}

// ---------------------------------------------------------------------------
// HMMA fp16 projection GEMM, 2 CTAs/SM. CTA tile 128m x 128pr x 64k,
// 2-stage cp.async pipeline (stage = Ahi | Alo | W = 55296B; total 111KB).
// 8 warps = 2m x 4n, warp tile 64m x 32pr. __launch_bounds__(256, 2).
// pr = hh*4+g; W natural row for pr: n = (pr&3)*512 + (pr>>2).
// ---------------------------------------------------------------------------
#define ROWB   144
#define TILEB  (128*ROWB)                 // 18432
#define STGB   (3*TILEB)                  // 55296
#define OFF_BIAS (2*STGB)                 // 110592
#define SMEM_PROJ (OFF_BIAS + 512)        // 111104

__global__ __launch_bounds__(256, 2) void proj_mma(
    const __half* __restrict__ Ah, const __half* __restrict__ Al,
    const __half* __restrict__ Wh,
    const float* __restrict__ b1, const float* __restrict__ b2)
{
    extern __shared__ __align__(128) char smp[];
    const uint32_t sb = smem_u32(smp);
    float* bias = (float*)(smp + OFF_BIAS);

    const int tid  = threadIdx.x;
    const int lane = tid & 31;
    const int w    = tid >> 5;
    const int m0   = blockIdx.x * 128;
    const int dir  = blockIdx.y >> 4;
    const int prG  = (blockIdx.y & 15) * 128;
    const int prB  = prG >> 2;
    const int wm   = (w >> 2) * 64;
    const int wn   = (w & 3) * 32;

    if (tid < 128) {
        int n = (tid & 3) * 512 + prB + (tid >> 2);
        bias[tid] = b1[dir * FOURH + n] + b2[dir * FOURH + n];
    }

    // 3072 chunks per stage (Ahi 1024, Alo 1024, W 1024); 12 per thread
    int cidx[12];
#pragma unroll
    for (int i = 0; i < 12; i++) cidx[i] = i * 256 + tid;

    auto load_stage = [&](int s, int kt) {
        uint32_t base = sb + (uint32_t)s * STGB;
#pragma unroll
        for (int i = 0; i < 12; i++) {
            int c = cidx[i];
            int cg = c & 7;
            int ct = c >> 10, row = (c >> 3) & 127;
            uint32_t dst = base + (uint32_t)ct * TILEB + (uint32_t)row * ROWB + (uint32_t)cg * 16;
            const __half* g;
            if (ct == 0)      g = Ah + (size_t)(m0 + row) * KP + kt * 64 + cg * 8;
            else if (ct == 1) g = Al + (size_t)(m0 + row) * KP + kt * 64 + cg * 8;
            else {
                int n = (row & 3) * 512 + prB + (row >> 2);
                g = Wh + (size_t)(dir * FOURH + n) * KP + kt * 64 + cg * 8;
            }
            cpa16(dst, g);
        }
        asm volatile("cp.async.commit_group;" ::: "memory");
    };

    float c[4][4][4];
#pragma unroll
    for (int mi = 0; mi < 4; mi++)
#pragma unroll
        for (int ni = 0; ni < 4; ni++)
#pragma unroll
            for (int j = 0; j < 4; j++) c[mi][ni][j] = 0.f;

    const uint32_t aRow  = (uint32_t)(wm + (lane & 15));
    const uint32_t aByte = (lane & 16) ? 16u : 0u;
    const uint32_t bRow  = (uint32_t)(wn + (lane & 7) + ((lane & 16) ? 8 : 0));
    const uint32_t bByte = (lane & 8) ? 16u : 0u;

    load_stage(0, 0);
    load_stage(1, 1);

    for (int kt = 0; kt < 16; kt++) {
        if (kt < 15) {
            asm volatile("cp.async.wait_group 1;" ::: "memory");
        } else {
            asm volatile("cp.async.wait_group 0;" ::: "memory");
        }
        __syncthreads();   // stage kt complete + visible

        uint32_t st = sb + (uint32_t)(kt & 1) * STGB;
#pragma unroll
        for (int ks = 0; ks < 4; ks++) {
            uint32_t kb = (uint32_t)(ks * 32);
            uint32_t ah[4][4], al[4][4], bh[2][4];
#pragma unroll
            for (int mi = 0; mi < 4; mi++) {
                uint32_t ra = (aRow + mi * 16) * ROWB + kb + aByte;
                ldm_x4(ah[mi][0], ah[mi][1], ah[mi][2], ah[mi][3], st + ra);
                ldm_x4(al[mi][0], al[mi][1], al[mi][2], al[mi][3], st + TILEB + ra);
            }
#pragma unroll
            for (int np = 0; np < 2; np++) {
                uint32_t rb = (bRow + np * 16) * ROWB + kb + bByte;
                ldm_x4(bh[np][0], bh[np][1], bh[np][2], bh[np][3], st + 2 * TILEB + rb);
            }
#pragma unroll
            for (int mi = 0; mi < 4; mi++)
#pragma unroll
                for (int ni = 0; ni < 4; ni++) {
                    int np = ni >> 1, o = (ni & 1) * 2;
                    MMA_F16(c[mi][ni], ah[mi], bh[np][o], bh[np][o + 1]);
                    MMA_F16(c[mi][ni], al[mi], bh[np][o], bh[np][o + 1]);
                }
        }
        __syncthreads();   // all readers done with stage kt

        if (kt + 2 < 16) load_stage(kt & 1, kt + 2);
    }

    float* outD = g_xproj + (size_t)dir * MM * FOURH;
#pragma unroll
    for (int mi = 0; mi < 4; mi++) {
        int row0 = m0 + wm + mi * 16 + (lane >> 2);
#pragma unroll
        for (int ni = 0; ni < 4; ni++) {
            int colL = wn + ni * 8 + (lane & 3) * 2;
            float bx = bias[colL], by = bias[colL + 1];
            *(float2*)&outD[(size_t)row0 * FOURH + prG + colL] =
                make_float2(c[mi][ni][0] + bx, c[mi][ni][1] + by);
            *(float2*)&outD[(size_t)(row0 + 8) * FOURH + prG + colL] =
                make_float2(c[mi][ni][2] + bx, c[mi][ni][3] + by);
        }
    }
}

// ---------------------------------------------------------------------------
// Persistent HMMA fp16 recurrence (unchanged from R13 — proven).
// grid = (64 blk, 2 dir), 256 threads (8 warps: 4m x 2n of m16n16).
// ---------------------------------------------------------------------------
#define SM_A   0                        // 4 chunks x (hi 17408 + lo 17408)
#define SM_W   139264                   // hi[32][1040] = 33280
#define SM_ST  172544                   // staging: hi 1KB | lo 1KB | f32 2KB
#define SM_MB  176640                   // 5 mbarriers
#define SMEM_LSTM 176704

__global__ __launch_bounds__(256, 1) void lstm_mma(
    const int* __restrict__ mask,     // [B][T]
    float*     __restrict__ outp,     // [T][B][2H] (mode 1)
    int mode)
{
    extern __shared__ __align__(128) char sm[];
    const uint32_t sb = smem_u32(sm);
    uint16_t* sHhi = (uint16_t*)(sm + SM_ST);
    uint16_t* sHlo = (uint16_t*)(sm + SM_ST + 1024);
    float*    sF32 = (float*)(sm + SM_ST + 2048);

    const int dir = blockIdx.y;
    const int blk = blockIdx.x;
    const int tid = threadIdx.x;
    const int lane = tid & 31;
    const int w = tid >> 5;
    const int wm = (w >> 1) * 16;       // batch offset
    const int wn = (w & 1) * 16;        // pr offset

    const uint32_t mb0 = sb + SM_MB;
    if (tid == 0) {
        for (int c = 0; c < 5; c++) mbar_init(mb0 + c * 8, 1);
        asm volatile("fence.proxy.async.shared::cta;" ::: "memory");
        mbar_expect_tx(mb0 + 32, (uint32_t)WSLAB);
        bulk_g2s(sb + SM_W, g_Wr + (size_t)(dir * 64 + blk) * WSLAB, (uint32_t)WSLAB, mb0 + 32);
    }
    __syncthreads();
    mbar_wait(mb0 + 32, 0);

    const uint32_t aRow  = (uint32_t)(wm + (lane & 15));
    const uint32_t aByte = (lane & 16) ? 16u : 0u;
    const uint32_t bRow  = (uint32_t)(wn + (lane & 7) + ((lane & 16) ? 8 : 0));
    const uint32_t bByte = (lane & 8) ? 16u : 0u;

    const float* xprjD = g_xproj + (size_t)dir * MM * FOURH;
    const char* hbase = g_hA + (size_t)dir * 2 * HA_SZ;
    unsigned* mycnt = &g_cnt[dir][blk >> 4];
    unsigned* spincnt = &g_cnt[dir][w & 3];

    const int r0    = wm + (lane >> 2);
    const int colp  = wn + (lane & 3) * 2;
    const int b_cell = r0 + ((lane & 1) << 3);
    const int hhA   = (wn >> 2) + ((lane >> 1) & 1);
    const int chunk = blk >> 4;
    const uint32_t klocByte = (uint32_t)((blk & 15) * 16);
    float cst[2] = {0.f, 0.f};

    for (int t = 0; t < TT; t++) {
        const int tt = dir ? (TT - 1 - t) : t;

        if (w < 4 && lane == 0) {
            unsigned target = 16u * (unsigned)t;
            unsigned v;
            do {
                asm volatile("ld.acquire.gpu.u32 %0, [%1];" : "=r"(v) : "l"(spincnt) : "memory");
            } while (v < target);
            asm volatile("fence.proxy.async.shared::cta;" ::: "memory");
            const char* src = hbase + (size_t)(t & 1) * HA_SZ + (size_t)w * CH_SZ;
            mbar_expect_tx(mb0 + w * 8, (uint32_t)CH_SZ);
            bulk_g2s(sb + SM_A + (uint32_t)w * CH_SZ, src, (uint32_t)CH_SZ, mb0 + w * 8);
        }

        float2 xg[2][2];
        {
            const float* base = xprjD + (size_t)tt * BB * FOURH + blk * 32;
#pragma unroll
            for (int ni = 0; ni < 2; ni++) {
                xg[ni][0] = *(const float2*)&base[(size_t)r0 * FOURH + colp + ni * 8];
                xg[ni][1] = *(const float2*)&base[(size_t)(r0 + 8) * FOURH + colp + ni * 8];
            }
        }
        const float mreg = (float)mask[b_cell * TT + tt];

        float cf[2][4];
#pragma unroll
        for (int ni = 0; ni < 2; ni++)
#pragma unroll
            for (int j = 0; j < 4; j++) cf[ni][j] = 0.f;

        const uint32_t par = (uint32_t)(t & 1);
#pragma unroll
        for (int c = 0; c < 4; c++) {
            mbar_wait(mb0 + c * 8, par);
            uint32_t baseA = sb + SM_A + (uint32_t)c * CH_SZ;
#pragma unroll
            for (int ks = 0; ks < 8; ks++) {
                uint32_t ah[4], al[4], bh[4];
                uint32_t ra = aRow * 272 + (uint32_t)ks * 32 + aByte;
                ldm_x4(ah[0], ah[1], ah[2], ah[3], baseA + ra);
                ldm_x4(al[0], al[1], al[2], al[3], baseA + CH_HALF + ra);
                uint32_t kb = ((uint32_t)(c * 8 + ks)) * 32 + bByte;
                ldm_x4(bh[0], bh[1], bh[2], bh[3], sb + SM_W + bRow * 1040 + kb);
#pragma unroll
                for (int ni = 0; ni < 2; ni++) {
                    int o = ni * 2;
                    MMA_F16(cf[ni], ah, bh[o], bh[o + 1]);
                    MMA_F16(cf[ni], al, bh[o], bh[o + 1]);
                }
            }
        }

#pragma unroll
        for (int ni = 0; ni < 2; ni++) {
            cf[ni][0] += xg[ni][0].x;  cf[ni][1] += xg[ni][0].y;
            cf[ni][2] += xg[ni][1].x;  cf[ni][3] += xg[ni][1].y;

            float sx = (lane & 1) ? cf[ni][0] : cf[ni][2];
            float sy = (lane & 1) ? cf[ni][1] : cf[ni][3];
            float rx = __shfl_xor_sync(0xffffffffu, sx, 1);
            float ry = __shfl_xor_sync(0xffffffffu, sy, 1);

            float gi, gf, gg, go;
            if (!(lane & 1)) { gi = cf[ni][0]; gf = cf[ni][1]; gg = rx; go = ry; }
            else             { gi = rx;        gf = ry;        gg = cf[ni][2]; go = cf[ni][3]; }

            float si = sig_(gi);
            float sf = sig_(gf);
            float so = sig_(go);
            float tg = 2.f * sig_(2.f * gg) - 1.f;
            float c2 = sf * cst[ni] + si * tg;
            float tc = 2.f * sig_(2.f * c2) - 1.f;
            float hn = so * tc * mreg;
            cst[ni] = c2 * mreg;

            int hh = hhA + ni * 2;
            __half hb = __float2half_rn(hn);
            __half lb = __float2half_rn(hn - __half2float(hb));
            sHhi[b_cell * 8 + hh] = __half_as_ushort(hb);
            sHlo[b_cell * 8 + hh] = __half_as_ushort(lb);
            if (mode) sF32[b_cell * 8 + hh] = hn;
        }
        __syncthreads();   // sync1: cells staged (also: all mbar_waits passed)

        char* hout = (char*)(hbase + (size_t)((t + 1) & 1) * HA_SZ + (size_t)chunk * CH_SZ);
        if (tid < 128) {
            if (tid < 64) {
                uint4 v = *(uint4*)((char*)sHhi + tid * 16);
                *(uint4*)(hout + tid * 272 + klocByte) = v;
            } else {
                int r = tid - 64;
                uint4 v = *(uint4*)((char*)sHlo + r * 16);
                *(uint4*)(hout + CH_HALF + r * 272 + klocByte) = v;
            }
            asm volatile("bar.sync 1, 128;" ::: "memory");
            if (tid == 0) {
                asm volatile("red.release.gpu.global.add.u32 [%0], %1;" :: "l"(mycnt), "r"(1u) : "memory");
            }
        } else if (mode == 0) {
            if (tid < 192) {
                int r = tid - 128;
                uint4 v = *(uint4*)((char*)sHhi + r * 16);
                *(uint4*)((char*)g_Ahi + ((size_t)(tt * 64 + r) * 1024 + dir * 512 + blk * 8) * 2) = v;
            } else {
                int r = tid - 192;
                uint4 v = *(uint4*)((char*)sHlo + r * 16);
                *(uint4*)((char*)g_Alo + ((size_t)(tt * 64 + r) * 1024 + dir * 512 + blk * 8) * 2) = v;
            }
        } else {
            int r = (tid - 128) >> 1, half = tid & 1;
            float4 v = *(float4*)((char*)sF32 + r * 32 + half * 16);
            *(float4*)&outp[((size_t)tt * 64 + r) * 1024 + dir * 512 + blk * 8 + half * 4] = v;
        }

        __syncthreads();   // sync2: guards sHhi/sF32 reuse + mbar re-arm
    }
}

// ---------------------------------------------------------------------------
// kernel_launch
// ---------------------------------------------------------------------------
extern "C" void kernel_launch(void* const* d_in, const int* in_sizes, int n_in,
                              void* d_out, int out_size)
{
    const float* x    = (const float*)d_in[0];
    const int*   mask = (const int*)  d_in[1];
    const float* w_ih = (const float*)d_in[2];
    const float* w_hh = (const float*)d_in[3];
    const float* b_ih = (const float*)d_in[4];
    const float* b_hh = (const float*)d_in[5];
    float* out = (float*)d_out;

    __half *pAh, *pAl, *pWh;
    cudaGetSymbolAddress((void**)&pAh, g_Ahi);
    cudaGetSymbolAddress((void**)&pAl, g_Alo);
    cudaGetSymbolAddress((void**)&pWh, g_Whi);

    cudaFuncSetAttribute(lstm_mma,
                         cudaFuncAttributeMaxDynamicSharedMemorySize, SMEM_LSTM);
    cudaFuncSetAttribute(proj_mma,
                         cudaFuncAttributeMaxDynamicSharedMemorySize, SMEM_PROJ);

    dim3 gproj(128, 32);
    dim3 gpers(64, 2);

    for (int layer = 0; layer < 2; layer++) {
        if (layer == 0) pack_f16_split<<<8192, 256>>>(x, pAh, pAl);
        // layer 1: g_Ahi/g_Alo already written by layer-0 lstm_mma

        pack_f16_single<<<2048, 256>>>(w_ih + (size_t)layer * 2 * FOURH * KP, pWh);
        pack_Wr<<<128, 256>>>(w_hh + (size_t)layer * 2 * FOURH * HH);

        proj_mma<<<gproj, 256, SMEM_PROJ>>>(
            pAh, pAl, pWh,
            b_ih + (size_t)layer * 2 * FOURH,
            b_hh + (size_t)layer * 2 * FOURH);

        lstm_mma<<<gpers, 256, SMEM_LSTM>>>(mask, (layer == 1) ? out : nullptr, layer);
    }
}